// round 7
// baseline (speedup 1.0000x reference)
#include <cuda_runtime.h>
#include <cuda_bf16.h>
#include <cstdint>

// ---------------------------------------------------------------------------
// GraphSAGE, 3 layers, mean aggregation.
//   agg = mean_{e: dst=d} h[src_e]            (CSR gather, atomic-free)
//   P   = h @ Wself                           (self GEMM, side stream)
//   h'  = act(agg @ Wneigh + P + b)           (neigh GEMM, main stream)
// Self GEMM overlaps CSR build (layer 0) / gather (all layers) via a second
// stream with event fork/join (captured into the harness's CUDA graph).
// ---------------------------------------------------------------------------

#define MAXN 100000
#define MAXE 1600000

__device__ float g_h1[(size_t)MAXN * 128];
__device__ float g_h2[(size_t)MAXN * 128];
__device__ float g_p  [(size_t)MAXN * 128];
__device__ float g_agg[(size_t)MAXN * 128];
__device__ float g_invdeg[MAXN];
__device__ int   g_degi[MAXN];
__device__ int   g_rowstart[MAXN + 1];
__device__ int   g_cursor[MAXN];
__device__ int   g_colsrc[MAXE];
__device__ int   g_blocksum[512];
__device__ int   g_blockoff[512];

// ---------------------------------------------------------------------------
// CSR build
// ---------------------------------------------------------------------------
__global__ void count_deg_kernel(const int* __restrict__ dst, int* __restrict__ degi, int E) {
    int i = blockIdx.x * blockDim.x + threadIdx.x;
    if (i < E) atomicAdd(&degi[dst[i]], 1);
}

__global__ void block_reduce_kernel(const int* __restrict__ degi,
                                    int* __restrict__ blocksum, int N) {
    __shared__ int s[256];
    int t = threadIdx.x;
    int i = blockIdx.x * 256 + t;
    s[t] = (i < N) ? degi[i] : 0;
    __syncthreads();
#pragma unroll
    for (int off = 128; off > 0; off >>= 1) {
        if (t < off) s[t] += s[t + off];
        __syncthreads();
    }
    if (t == 0) blocksum[blockIdx.x] = s[0];
}

__global__ void scan_blocksums_kernel(const int* __restrict__ blocksum,
                                      int* __restrict__ blockoff, int nb) {
    __shared__ int s[512];
    int t = threadIdx.x;
    int v = (t < nb) ? blocksum[t] : 0;
    s[t] = v;
    __syncthreads();
    for (int off = 1; off < 512; off <<= 1) {
        int u = (t >= off) ? s[t - off] : 0;
        __syncthreads();
        s[t] += u;
        __syncthreads();
    }
    if (t < nb) blockoff[t] = s[t] - v;
}

__global__ void scan_write_kernel(const int* __restrict__ degi,
                                  const int* __restrict__ blockoff,
                                  int* __restrict__ rowstart,
                                  float* __restrict__ invdeg, int N) {
    __shared__ int s[256];
    int t = threadIdx.x;
    int i = blockIdx.x * 256 + t;
    int v = (i < N) ? degi[i] : 0;
    s[t] = v;
    __syncthreads();
    for (int off = 1; off < 256; off <<= 1) {
        int u = (t >= off) ? s[t - off] : 0;
        __syncthreads();
        s[t] += u;
        __syncthreads();
    }
    if (i < N) {
        int excl = s[t] - v + blockoff[blockIdx.x];
        rowstart[i] = excl;
        invdeg[i] = 1.0f / fmaxf((float)v, 1.0f);
        if (i == N - 1) rowstart[N] = excl + v;
    }
}

__global__ void fill_kernel(const int* __restrict__ src,
                            const int* __restrict__ dst,
                            const int* __restrict__ rowstart,
                            int* __restrict__ cursor,
                            int* __restrict__ colsrc, int E) {
    int i = blockIdx.x * blockDim.x + threadIdx.x;
    if (i >= E) return;
    int d = dst[i];
    int pos = rowstart[d] + atomicAdd(&cursor[d], 1);
    colsrc[pos] = src[i];
}

// ---------------------------------------------------------------------------
// gather: agg[n] = inv_deg[n] * sum_{j in row(n)} h[colsrc[j]]   (warp/node)
// 8-deep unroll for MLP.
// ---------------------------------------------------------------------------
__global__ void gather_kernel(const float* __restrict__ h,
                              const int* __restrict__ rowstart,
                              const int* __restrict__ colsrc,
                              const float* __restrict__ invdeg,
                              float* __restrict__ agg, int N) {
    int warp = (blockIdx.x * blockDim.x + threadIdx.x) >> 5;
    int lane = threadIdx.x & 31;
    if (warp >= N) return;
    int beg = rowstart[warp];
    int end = rowstart[warp + 1];

    const float* hb = h + lane * 4;
    float4 acc = make_float4(0.f, 0.f, 0.f, 0.f);
    int j = beg;
    for (; j + 8 <= end; j += 8) {
        int s0 = __ldg(colsrc + j + 0);
        int s1 = __ldg(colsrc + j + 1);
        int s2 = __ldg(colsrc + j + 2);
        int s3 = __ldg(colsrc + j + 3);
        int s4 = __ldg(colsrc + j + 4);
        int s5 = __ldg(colsrc + j + 5);
        int s6 = __ldg(colsrc + j + 6);
        int s7 = __ldg(colsrc + j + 7);
        float4 v0 = *(const float4*)(hb + (size_t)s0 * 128);
        float4 v1 = *(const float4*)(hb + (size_t)s1 * 128);
        float4 v2 = *(const float4*)(hb + (size_t)s2 * 128);
        float4 v3 = *(const float4*)(hb + (size_t)s3 * 128);
        float4 v4 = *(const float4*)(hb + (size_t)s4 * 128);
        float4 v5 = *(const float4*)(hb + (size_t)s5 * 128);
        float4 v6 = *(const float4*)(hb + (size_t)s6 * 128);
        float4 v7 = *(const float4*)(hb + (size_t)s7 * 128);
        acc.x += (v0.x + v1.x) + (v2.x + v3.x) + ((v4.x + v5.x) + (v6.x + v7.x));
        acc.y += (v0.y + v1.y) + (v2.y + v3.y) + ((v4.y + v5.y) + (v6.y + v7.y));
        acc.z += (v0.z + v1.z) + (v2.z + v3.z) + ((v4.z + v5.z) + (v6.z + v7.z));
        acc.w += (v0.w + v1.w) + (v2.w + v3.w) + ((v4.w + v5.w) + (v6.w + v7.w));
    }
    for (; j + 4 <= end; j += 4) {
        int s0 = __ldg(colsrc + j + 0);
        int s1 = __ldg(colsrc + j + 1);
        int s2 = __ldg(colsrc + j + 2);
        int s3 = __ldg(colsrc + j + 3);
        float4 v0 = *(const float4*)(hb + (size_t)s0 * 128);
        float4 v1 = *(const float4*)(hb + (size_t)s1 * 128);
        float4 v2 = *(const float4*)(hb + (size_t)s2 * 128);
        float4 v3 = *(const float4*)(hb + (size_t)s3 * 128);
        acc.x += (v0.x + v1.x) + (v2.x + v3.x);
        acc.y += (v0.y + v1.y) + (v2.y + v3.y);
        acc.z += (v0.z + v1.z) + (v2.z + v3.z);
        acc.w += (v0.w + v1.w) + (v2.w + v3.w);
    }
    for (; j < end; j++) {
        int s = __ldg(colsrc + j);
        float4 v = *(const float4*)(hb + (size_t)s * 128);
        acc.x += v.x; acc.y += v.y; acc.z += v.z; acc.w += v.w;
    }
    float id = invdeg[warp];
    acc.x *= id; acc.y *= id; acc.z *= id; acc.w *= id;
    *(float4*)(agg + (size_t)warp * 128 + lane * 4) = acc;
}

// ---------------------------------------------------------------------------
// tf32 helpers
// ---------------------------------------------------------------------------
__device__ __forceinline__ uint32_t f2tf32(float x) {
    uint32_t u;
    asm("cvt.rna.tf32.f32 %0, %1;" : "=r"(u) : "f"(x));
    return u;
}

__device__ __forceinline__ void mma_tf32(float& c0, float& c1, float& c2, float& c3,
                                         uint32_t a0, uint32_t a1, uint32_t a2, uint32_t a3,
                                         uint32_t b0, uint32_t b1) {
    asm volatile(
        "mma.sync.aligned.m16n8k8.row.col.f32.tf32.tf32.f32 "
        "{%0,%1,%2,%3}, {%4,%5,%6,%7}, {%8,%9}, {%0,%1,%2,%3};\n"
        : "+f"(c0), "+f"(c1), "+f"(c2), "+f"(c3)
        : "r"(a0), "r"(a1), "r"(a2), "r"(a3), "r"(b0), "r"(b1));
}

// ---------------------------------------------------------------------------
// single-A tf32 GEMM:  out[M,BN] = A[M,128] @ W[128,BN]  (+ P + bias, relu)
// Block 128 x BN, 256 threads = 8 warps (4m x 2n), warp tile 32 x BN/2.
// mma m16n8k8 tf32, K=128 tiled at KT=16, double-buffered, reg prefetch.
// ---------------------------------------------------------------------------
template <int BN, bool RELU, bool ADDP, bool BIAS>
__launch_bounds__(256, 2)
__global__ void gemm1_kernel(const float* __restrict__ A,
                             const float* __restrict__ W,
                             const float* __restrict__ P,
                             const float* __restrict__ bias,
                             float* __restrict__ out, int M) {
    constexpr int KT   = 16;
    constexpr int NS   = 8;            // 128 / KT
    constexpr int APAD = 4;
    constexpr int BPAD = 8;
    constexpr int NF   = BN / 16;
    constexpr int NB4  = (KT * BN / 4) / 256;

    __shared__ uint32_t As[2][128][KT + APAD];
    __shared__ uint32_t Bs[2][KT][BN + BPAD];

    const int tid  = threadIdx.x;
    const int wid  = tid >> 5;
    const int lane = tid & 31;
    const int g    = lane >> 2;
    const int t4   = lane & 3;
    const int warpM = wid & 3;
    const int warpN = wid >> 2;
    const int rowBase = blockIdx.x * 128;

    float acc[2][NF][4];
#pragma unroll
    for (int mf = 0; mf < 2; mf++)
#pragma unroll
        for (int nf = 0; nf < NF; nf++)
#pragma unroll
            for (int r = 0; r < 4; r++) acc[mf][nf][r] = 0.f;

    float4 ra[2];
    float4 rb[NB4];

    // ---- prologue: stage 0 ----
    {
#pragma unroll
        for (int i = 0; i < 2; i++) {
            int f = tid + i * 256;
            int r = f >> 2, kq = f & 3;
            int row = rowBase + r;
            float4 v = make_float4(0.f, 0.f, 0.f, 0.f);
            if (row < M) v = *(const float4*)(A + (size_t)row * 128 + kq * 4);
            uint32_t* p = &As[0][r][kq * 4];
            p[0] = f2tf32(v.x); p[1] = f2tf32(v.y);
            p[2] = f2tf32(v.z); p[3] = f2tf32(v.w);
        }
#pragma unroll
        for (int i = 0; i < NB4; i++) {
            int f = tid + i * 256;
            int kk = f / (BN / 4), cc = f % (BN / 4);
            float4 v = *(const float4*)(W + (size_t)kk * BN + cc * 4);
            uint32_t* p = &Bs[0][kk][cc * 4];
            p[0] = f2tf32(v.x); p[1] = f2tf32(v.y);
            p[2] = f2tf32(v.z); p[3] = f2tf32(v.w);
        }
    }
    __syncthreads();

    // ---- main loop ----
#pragma unroll 1
    for (int s = 0; s < NS; s++) {
        const int buf = s & 1;

        if (s + 1 < NS) {
            const int k0 = (s + 1) * KT;
#pragma unroll
            for (int i = 0; i < 2; i++) {
                int f = tid + i * 256;
                int r = f >> 2, kq = f & 3;
                int row = rowBase + r;
                ra[i] = make_float4(0.f, 0.f, 0.f, 0.f);
                if (row < M) ra[i] = *(const float4*)(A + (size_t)row * 128 + k0 + kq * 4);
            }
#pragma unroll
            for (int i = 0; i < NB4; i++) {
                int f = tid + i * 256;
                int kk = f / (BN / 4), cc = f % (BN / 4);
                rb[i] = *(const float4*)(W + (size_t)(k0 + kk) * BN + cc * 4);
            }
        }

#pragma unroll
        for (int k8 = 0; k8 < 2; k8++) {
            const int kb = k8 * 8;
            uint32_t a[2][4];
#pragma unroll
            for (int mf = 0; mf < 2; mf++) {
                int r0 = warpM * 32 + mf * 16 + g;
                a[mf][0] = As[buf][r0][kb + t4];
                a[mf][1] = As[buf][r0 + 8][kb + t4];
                a[mf][2] = As[buf][r0][kb + t4 + 4];
                a[mf][3] = As[buf][r0 + 8][kb + t4 + 4];
            }
#pragma unroll
            for (int nf = 0; nf < NF; nf++) {
                int cb = warpN * (BN / 2) + nf * 8 + g;
                uint32_t b0 = Bs[buf][kb + t4][cb];
                uint32_t b1 = Bs[buf][kb + t4 + 4][cb];
#pragma unroll
                for (int mf = 0; mf < 2; mf++) {
                    mma_tf32(acc[mf][nf][0], acc[mf][nf][1],
                             acc[mf][nf][2], acc[mf][nf][3],
                             a[mf][0], a[mf][1], a[mf][2], a[mf][3], b0, b1);
                }
            }
        }

        if (s + 1 < NS) {
            const int nbuf = buf ^ 1;
#pragma unroll
            for (int i = 0; i < 2; i++) {
                int f = tid + i * 256;
                int r = f >> 2, kq = f & 3;
                uint32_t* p = &As[nbuf][r][kq * 4];
                p[0] = f2tf32(ra[i].x); p[1] = f2tf32(ra[i].y);
                p[2] = f2tf32(ra[i].z); p[3] = f2tf32(ra[i].w);
            }
#pragma unroll
            for (int i = 0; i < NB4; i++) {
                int f = tid + i * 256;
                int kk = f / (BN / 4), cc = f % (BN / 4);
                uint32_t* p = &Bs[nbuf][kk][cc * 4];
                p[0] = f2tf32(rb[i].x); p[1] = f2tf32(rb[i].y);
                p[2] = f2tf32(rb[i].z); p[3] = f2tf32(rb[i].w);
            }
            __syncthreads();
        }
    }

    // ---- epilogue ----
#pragma unroll
    for (int nf = 0; nf < NF; nf++) {
        int col = warpN * (BN / 2) + nf * 8 + t4 * 2;
        float2 bv = make_float2(0.f, 0.f);
        if (BIAS) bv = *(const float2*)(bias + col);
#pragma unroll
        for (int mf = 0; mf < 2; mf++) {
            int r0 = rowBase + warpM * 32 + mf * 16 + g;
            float2 v0 = make_float2(acc[mf][nf][0] + bv.x, acc[mf][nf][1] + bv.y);
            float2 v1 = make_float2(acc[mf][nf][2] + bv.x, acc[mf][nf][3] + bv.y);
            if (r0 < M) {
                if (ADDP) {
                    float2 pv = *(const float2*)(P + (size_t)r0 * BN + col);
                    v0.x += pv.x; v0.y += pv.y;
                }
                if (RELU) { v0.x = fmaxf(v0.x, 0.f); v0.y = fmaxf(v0.y, 0.f); }
                *(float2*)(out + (size_t)r0 * BN + col) = v0;
            }
            if (r0 + 8 < M) {
                if (ADDP) {
                    float2 pv = *(const float2*)(P + (size_t)(r0 + 8) * BN + col);
                    v1.x += pv.x; v1.y += pv.y;
                }
                if (RELU) { v1.x = fmaxf(v1.x, 0.f); v1.y = fmaxf(v1.y, 0.f); }
                *(float2*)(out + (size_t)(r0 + 8) * BN + col) = v1;
            }
        }
    }
}

// ---------------------------------------------------------------------------
// launch
// ---------------------------------------------------------------------------
extern "C" void kernel_launch(void* const* d_in, const int* in_sizes, int n_in,
                              void* d_out, int out_size) {
    const float* x   = (const float*)d_in[0];
    const int*   src = (const int*)d_in[1];
    const int*   dst = (const int*)d_in[2];
    const float* Ws0 = (const float*)d_in[3];
    const float* Wn0 = (const float*)d_in[4];
    const float* b0  = (const float*)d_in[5];
    const float* Ws1 = (const float*)d_in[6];
    const float* Wn1 = (const float*)d_in[7];
    const float* b1  = (const float*)d_in[8];
    const float* Ws2 = (const float*)d_in[9];
    const float* Wn2 = (const float*)d_in[10];
    const float* b2  = (const float*)d_in[11];
    float* out = (float*)d_out;

    const int M = in_sizes[0] / 128;   // 100000
    const int E = in_sizes[1];         // 1600000

    float *h1, *h2, *P, *agg, *invdeg;
    int *degi, *rowstart, *cursor, *colsrc, *blocksum, *blockoff;
    cudaGetSymbolAddress((void**)&h1,  g_h1);
    cudaGetSymbolAddress((void**)&h2,  g_h2);
    cudaGetSymbolAddress((void**)&P,   g_p);
    cudaGetSymbolAddress((void**)&agg, g_agg);
    cudaGetSymbolAddress((void**)&invdeg, g_invdeg);
    cudaGetSymbolAddress((void**)&degi, g_degi);
    cudaGetSymbolAddress((void**)&rowstart, g_rowstart);
    cudaGetSymbolAddress((void**)&cursor, g_cursor);
    cudaGetSymbolAddress((void**)&colsrc, g_colsrc);
    cudaGetSymbolAddress((void**)&blocksum, g_blocksum);
    cudaGetSymbolAddress((void**)&blockoff, g_blockoff);

    // side stream + events (host-side objects, created once; no device alloc)
    static cudaStream_t s2 = nullptr;
    static cudaEvent_t evFork, evS0, evS1, evS2, evH0, evH1;
    if (!s2) {
        cudaStreamCreateWithFlags(&s2, cudaStreamNonBlocking);
        cudaEventCreateWithFlags(&evFork, cudaEventDisableTiming);
        cudaEventCreateWithFlags(&evS0,   cudaEventDisableTiming);
        cudaEventCreateWithFlags(&evS1,   cudaEventDisableTiming);
        cudaEventCreateWithFlags(&evS2,   cudaEventDisableTiming);
        cudaEventCreateWithFlags(&evH0,   cudaEventDisableTiming);
        cudaEventCreateWithFlags(&evH1,   cudaEventDisableTiming);
    }

    const int gemmBlocks   = (M + 127) / 128;
    const int edgeBlocks   = (E + 255) / 256;
    const int gatherBlocks = (M * 32 + 255) / 256;
    const int scanBlocks   = (M + 255) / 256;

    // ---- fork side stream (independent of CSR chain) ----
    cudaEventRecord(evFork, 0);
    cudaStreamWaitEvent(s2, evFork, 0);

    // ---- main stream: CSR build ----
    cudaMemsetAsync(degi, 0, (size_t)M * sizeof(int));
    cudaMemsetAsync(cursor, 0, (size_t)M * sizeof(int));
    count_deg_kernel<<<edgeBlocks, 256>>>(dst, degi, E);
    block_reduce_kernel<<<scanBlocks, 256>>>(degi, blocksum, M);
    scan_blocksums_kernel<<<1, 512>>>(blocksum, blockoff, scanBlocks);
    scan_write_kernel<<<scanBlocks, 256>>>(degi, blockoff, rowstart, invdeg, M);
    fill_kernel<<<edgeBlocks, 256>>>(src, dst, rowstart, cursor, colsrc, E);

    // ---- layer 0 ----
    gemm1_kernel<128, false, false, false><<<gemmBlocks, 256, 0, s2>>>(
        x, Ws0, nullptr, nullptr, P, M);                    // P = x@Ws0  (overlaps CSR)
    cudaEventRecord(evS0, s2);
    gather_kernel<<<gatherBlocks, 256>>>(x, rowstart, colsrc, invdeg, agg, M);
    cudaStreamWaitEvent(0, evS0, 0);
    gemm1_kernel<128, true, true, true><<<gemmBlocks, 256>>>(
        agg, Wn0, P, b0, h1, M);                            // h1 = relu(agg@Wn0 + P + b0)
    cudaEventRecord(evH0, 0);

    // ---- layer 1 ----
    cudaStreamWaitEvent(s2, evH0, 0);
    gemm1_kernel<128, false, false, false><<<gemmBlocks, 256, 0, s2>>>(
        h1, Ws1, nullptr, nullptr, P, M);                   // overlaps gather below
    cudaEventRecord(evS1, s2);
    gather_kernel<<<gatherBlocks, 256>>>(h1, rowstart, colsrc, invdeg, agg, M);
    cudaStreamWaitEvent(0, evS1, 0);
    gemm1_kernel<128, true, true, true><<<gemmBlocks, 256>>>(
        agg, Wn1, P, b1, h2, M);
    cudaEventRecord(evH1, 0);

    // ---- layer 2 (BN=64, no relu) ----
    cudaStreamWaitEvent(s2, evH1, 0);
    gemm1_kernel<64, false, false, false><<<gemmBlocks, 256, 0, s2>>>(
        h2, Ws2, nullptr, nullptr, P, M);
    cudaEventRecord(evS2, s2);
    gather_kernel<<<gatherBlocks, 256>>>(h2, rowstart, colsrc, invdeg, agg, M);
    cudaStreamWaitEvent(0, evS2, 0);
    gemm1_kernel<64, false, true, true><<<gemmBlocks, 256>>>(
        agg, Wn2, P, b2, out, M);
}

// round 8
// speedup vs baseline: 1.0914x; 1.0914x over previous
#include <cuda_runtime.h>
#include <cuda_bf16.h>
#include <cstdint>

// ---------------------------------------------------------------------------
// GraphSAGE, 3 layers, mean aggregation. Aggregate-then-transform:
//   agg = mean_{e: dst=d} h[src_e]          (CSR gather, atomic-free)
//   h'  = act([h | agg] @ [Wself; Wneigh] + b)   (dual-A tf32 MMA GEMM, K=256)
// Single stream; chip-wide two-level scan for CSR.
// ---------------------------------------------------------------------------

#define MAXN 100000
#define MAXE 1600000

__device__ float g_h1[(size_t)MAXN * 128];
__device__ float g_h2[(size_t)MAXN * 128];
__device__ float g_agg[(size_t)MAXN * 128];
__device__ float g_invdeg[MAXN];
__device__ int   g_tmpint[2 * MAXN];        // [0:MAXN) degi, [MAXN:2MAXN) cursor
__device__ int   g_rowstart[MAXN + 1];
__device__ int   g_colsrc[MAXE];
__device__ int   g_blocksum[512];
__device__ int   g_blockoff[512];

// ---------------------------------------------------------------------------
// CSR build
// ---------------------------------------------------------------------------
__global__ void count_deg_kernel(const int* __restrict__ dst, int* __restrict__ degi, int E) {
    int i = blockIdx.x * blockDim.x + threadIdx.x;
    if (i < E) atomicAdd(&degi[dst[i]], 1);
}

__global__ void block_reduce_kernel(const int* __restrict__ degi,
                                    int* __restrict__ blocksum, int N) {
    __shared__ int s[256];
    int t = threadIdx.x;
    int i = blockIdx.x * 256 + t;
    s[t] = (i < N) ? degi[i] : 0;
    __syncthreads();
#pragma unroll
    for (int off = 128; off > 0; off >>= 1) {
        if (t < off) s[t] += s[t + off];
        __syncthreads();
    }
    if (t == 0) blocksum[blockIdx.x] = s[0];
}

__global__ void scan_blocksums_kernel(const int* __restrict__ blocksum,
                                      int* __restrict__ blockoff, int nb) {
    __shared__ int s[512];
    int t = threadIdx.x;
    int v = (t < nb) ? blocksum[t] : 0;
    s[t] = v;
    __syncthreads();
    for (int off = 1; off < 512; off <<= 1) {
        int u = (t >= off) ? s[t - off] : 0;
        __syncthreads();
        s[t] += u;
        __syncthreads();
    }
    if (t < nb) blockoff[t] = s[t] - v;
}

__global__ void scan_write_kernel(const int* __restrict__ degi,
                                  const int* __restrict__ blockoff,
                                  int* __restrict__ rowstart,
                                  float* __restrict__ invdeg, int N) {
    __shared__ int s[256];
    int t = threadIdx.x;
    int i = blockIdx.x * 256 + t;
    int v = (i < N) ? degi[i] : 0;
    s[t] = v;
    __syncthreads();
    for (int off = 1; off < 256; off <<= 1) {
        int u = (t >= off) ? s[t - off] : 0;
        __syncthreads();
        s[t] += u;
        __syncthreads();
    }
    if (i < N) {
        int excl = s[t] - v + blockoff[blockIdx.x];
        rowstart[i] = excl;
        invdeg[i] = 1.0f / fmaxf((float)v, 1.0f);
        if (i == N - 1) rowstart[N] = excl + v;
    }
}

__global__ void fill_kernel(const int* __restrict__ src,
                            const int* __restrict__ dst,
                            const int* __restrict__ rowstart,
                            int* __restrict__ cursor,
                            int* __restrict__ colsrc, int E) {
    int i = blockIdx.x * blockDim.x + threadIdx.x;
    if (i >= E) return;
    int d = dst[i];
    int pos = rowstart[d] + atomicAdd(&cursor[d], 1);
    colsrc[pos] = src[i];
}

// ---------------------------------------------------------------------------
// gather: agg[n] = inv_deg[n] * sum_{j in row(n)} h[colsrc[j]]   (warp/node)
// 8-deep unroll: 8 outstanding LDG.128 per lane.
// ---------------------------------------------------------------------------
__global__ void gather_kernel(const float* __restrict__ h,
                              const int* __restrict__ rowstart,
                              const int* __restrict__ colsrc,
                              const float* __restrict__ invdeg,
                              float* __restrict__ agg, int N) {
    int warp = (blockIdx.x * blockDim.x + threadIdx.x) >> 5;
    int lane = threadIdx.x & 31;
    if (warp >= N) return;
    int beg = rowstart[warp];
    int end = rowstart[warp + 1];

    const float* hb = h + lane * 4;
    float4 acc = make_float4(0.f, 0.f, 0.f, 0.f);
    int j = beg;
    for (; j + 8 <= end; j += 8) {
        int s0 = __ldg(colsrc + j + 0);
        int s1 = __ldg(colsrc + j + 1);
        int s2 = __ldg(colsrc + j + 2);
        int s3 = __ldg(colsrc + j + 3);
        int s4 = __ldg(colsrc + j + 4);
        int s5 = __ldg(colsrc + j + 5);
        int s6 = __ldg(colsrc + j + 6);
        int s7 = __ldg(colsrc + j + 7);
        float4 v0 = *(const float4*)(hb + (size_t)s0 * 128);
        float4 v1 = *(const float4*)(hb + (size_t)s1 * 128);
        float4 v2 = *(const float4*)(hb + (size_t)s2 * 128);
        float4 v3 = *(const float4*)(hb + (size_t)s3 * 128);
        float4 v4 = *(const float4*)(hb + (size_t)s4 * 128);
        float4 v5 = *(const float4*)(hb + (size_t)s5 * 128);
        float4 v6 = *(const float4*)(hb + (size_t)s6 * 128);
        float4 v7 = *(const float4*)(hb + (size_t)s7 * 128);
        acc.x += (v0.x + v1.x) + (v2.x + v3.x) + ((v4.x + v5.x) + (v6.x + v7.x));
        acc.y += (v0.y + v1.y) + (v2.y + v3.y) + ((v4.y + v5.y) + (v6.y + v7.y));
        acc.z += (v0.z + v1.z) + (v2.z + v3.z) + ((v4.z + v5.z) + (v6.z + v7.z));
        acc.w += (v0.w + v1.w) + (v2.w + v3.w) + ((v4.w + v5.w) + (v6.w + v7.w));
    }
    for (; j + 4 <= end; j += 4) {
        int s0 = __ldg(colsrc + j + 0);
        int s1 = __ldg(colsrc + j + 1);
        int s2 = __ldg(colsrc + j + 2);
        int s3 = __ldg(colsrc + j + 3);
        float4 v0 = *(const float4*)(hb + (size_t)s0 * 128);
        float4 v1 = *(const float4*)(hb + (size_t)s1 * 128);
        float4 v2 = *(const float4*)(hb + (size_t)s2 * 128);
        float4 v3 = *(const float4*)(hb + (size_t)s3 * 128);
        acc.x += (v0.x + v1.x) + (v2.x + v3.x);
        acc.y += (v0.y + v1.y) + (v2.y + v3.y);
        acc.z += (v0.z + v1.z) + (v2.z + v3.z);
        acc.w += (v0.w + v1.w) + (v2.w + v3.w);
    }
    for (; j < end; j++) {
        int s = __ldg(colsrc + j);
        float4 v = *(const float4*)(hb + (size_t)s * 128);
        acc.x += v.x; acc.y += v.y; acc.z += v.z; acc.w += v.w;
    }
    float id = invdeg[warp];
    acc.x *= id; acc.y *= id; acc.z *= id; acc.w *= id;
    *(float4*)(agg + (size_t)warp * 128 + lane * 4) = acc;
}

// ---------------------------------------------------------------------------
// tf32 helpers
// ---------------------------------------------------------------------------
__device__ __forceinline__ uint32_t f2tf32(float x) {
    uint32_t u;
    asm("cvt.rna.tf32.f32 %0, %1;" : "=r"(u) : "f"(x));
    return u;
}

__device__ __forceinline__ void mma_tf32(float& c0, float& c1, float& c2, float& c3,
                                         uint32_t a0, uint32_t a1, uint32_t a2, uint32_t a3,
                                         uint32_t b0, uint32_t b1) {
    asm volatile(
        "mma.sync.aligned.m16n8k8.row.col.f32.tf32.tf32.f32 "
        "{%0,%1,%2,%3}, {%4,%5,%6,%7}, {%8,%9}, {%0,%1,%2,%3};\n"
        : "+f"(c0), "+f"(c1), "+f"(c2), "+f"(c3)
        : "r"(a0), "r"(a1), "r"(a2), "r"(a3), "r"(b0), "r"(b1));
}

// ---------------------------------------------------------------------------
// dual-A tf32 GEMM:  out[M,BN] = A1[M,128]@W1[128,BN] + A2[M,128]@W2[128,BN]+b
// Block 128 x BN, 256 threads = 8 warps (4m x 2n), warp tile 32 x BN/2.
// mma m16n8k8 tf32, K tiled at KT=16, double-buffered, register prefetch.
// ---------------------------------------------------------------------------
template <int BN, bool RELU>
__launch_bounds__(256, 2)
__global__ void gemm_tc_kernel(const float* __restrict__ A1,
                               const float* __restrict__ A2,
                               const float* __restrict__ W1,
                               const float* __restrict__ W2,
                               const float* __restrict__ bias,
                               float* __restrict__ out, int M) {
    constexpr int KT  = 16;
    constexpr int NS  = 16;            // 256 / KT
    constexpr int APAD = 4;
    constexpr int BPAD = 8;
    constexpr int NF  = BN / 16;
    constexpr int NB4 = (KT * BN / 4) / 256;

    __shared__ uint32_t As[2][128][KT + APAD];
    __shared__ uint32_t Bs[2][KT][BN + BPAD];

    const int tid  = threadIdx.x;
    const int wid  = tid >> 5;
    const int lane = tid & 31;
    const int g    = lane >> 2;
    const int t4   = lane & 3;
    const int warpM = wid & 3;
    const int warpN = wid >> 2;
    const int rowBase = blockIdx.x * 128;

    float acc[2][NF][4];
#pragma unroll
    for (int mf = 0; mf < 2; mf++)
#pragma unroll
        for (int nf = 0; nf < NF; nf++)
#pragma unroll
            for (int r = 0; r < 4; r++) acc[mf][nf][r] = 0.f;

    float4 ra[2];
    float4 rb[NB4];

    // ---- prologue: stage 0 (A1 / W1) ----
    {
#pragma unroll
        for (int i = 0; i < 2; i++) {
            int f = tid + i * 256;
            int r = f >> 2, kq = f & 3;
            int row = rowBase + r;
            float4 v = make_float4(0.f, 0.f, 0.f, 0.f);
            if (row < M) v = *(const float4*)(A1 + (size_t)row * 128 + kq * 4);
            uint32_t* p = &As[0][r][kq * 4];
            p[0] = f2tf32(v.x); p[1] = f2tf32(v.y);
            p[2] = f2tf32(v.z); p[3] = f2tf32(v.w);
        }
#pragma unroll
        for (int i = 0; i < NB4; i++) {
            int f = tid + i * 256;
            int kk = f / (BN / 4), cc = f % (BN / 4);
            float4 v = *(const float4*)(W1 + (size_t)kk * BN + cc * 4);
            uint32_t* p = &Bs[0][kk][cc * 4];
            p[0] = f2tf32(v.x); p[1] = f2tf32(v.y);
            p[2] = f2tf32(v.z); p[3] = f2tf32(v.w);
        }
    }
    __syncthreads();

    // ---- main loop over 16 stages ----
#pragma unroll 1
    for (int s = 0; s < NS; s++) {
        const int buf = s & 1;

        if (s + 1 < NS) {
            const float* A = (s + 1 < 8) ? A1 : A2;
            const float* W = (s + 1 < 8) ? W1 : W2;
            const int k0 = ((s + 1) & 7) * KT;
#pragma unroll
            for (int i = 0; i < 2; i++) {
                int f = tid + i * 256;
                int r = f >> 2, kq = f & 3;
                int row = rowBase + r;
                ra[i] = make_float4(0.f, 0.f, 0.f, 0.f);
                if (row < M) ra[i] = *(const float4*)(A + (size_t)row * 128 + k0 + kq * 4);
            }
#pragma unroll
            for (int i = 0; i < NB4; i++) {
                int f = tid + i * 256;
                int kk = f / (BN / 4), cc = f % (BN / 4);
                rb[i] = *(const float4*)(W + (size_t)(k0 + kk) * BN + cc * 4);
            }
        }

#pragma unroll
        for (int k8 = 0; k8 < 2; k8++) {
            const int kb = k8 * 8;
            uint32_t a[2][4];
#pragma unroll
            for (int mf = 0; mf < 2; mf++) {
                int r0 = warpM * 32 + mf * 16 + g;
                a[mf][0] = As[buf][r0][kb + t4];
                a[mf][1] = As[buf][r0 + 8][kb + t4];
                a[mf][2] = As[buf][r0][kb + t4 + 4];
                a[mf][3] = As[buf][r0 + 8][kb + t4 + 4];
            }
#pragma unroll
            for (int nf = 0; nf < NF; nf++) {
                int cb = warpN * (BN / 2) + nf * 8 + g;
                uint32_t b0 = Bs[buf][kb + t4][cb];
                uint32_t b1 = Bs[buf][kb + t4 + 4][cb];
#pragma unroll
                for (int mf = 0; mf < 2; mf++) {
                    mma_tf32(acc[mf][nf][0], acc[mf][nf][1],
                             acc[mf][nf][2], acc[mf][nf][3],
                             a[mf][0], a[mf][1], a[mf][2], a[mf][3], b0, b1);
                }
            }
        }

        if (s + 1 < NS) {
            const int nbuf = buf ^ 1;
#pragma unroll
            for (int i = 0; i < 2; i++) {
                int f = tid + i * 256;
                int r = f >> 2, kq = f & 3;
                uint32_t* p = &As[nbuf][r][kq * 4];
                p[0] = f2tf32(ra[i].x); p[1] = f2tf32(ra[i].y);
                p[2] = f2tf32(ra[i].z); p[3] = f2tf32(ra[i].w);
            }
#pragma unroll
            for (int i = 0; i < NB4; i++) {
                int f = tid + i * 256;
                int kk = f / (BN / 4), cc = f % (BN / 4);
                uint32_t* p = &Bs[nbuf][kk][cc * 4];
                p[0] = f2tf32(rb[i].x); p[1] = f2tf32(rb[i].y);
                p[2] = f2tf32(rb[i].z); p[3] = f2tf32(rb[i].w);
            }
            __syncthreads();
        }
    }

    // ---- epilogue ----
#pragma unroll
    for (int nf = 0; nf < NF; nf++) {
        int col = warpN * (BN / 2) + nf * 8 + t4 * 2;
        float2 bv = *(const float2*)(bias + col);
#pragma unroll
        for (int mf = 0; mf < 2; mf++) {
            int r0 = rowBase + warpM * 32 + mf * 16 + g;
            float2 v0 = make_float2(acc[mf][nf][0] + bv.x, acc[mf][nf][1] + bv.y);
            float2 v1 = make_float2(acc[mf][nf][2] + bv.x, acc[mf][nf][3] + bv.y);
            if (RELU) {
                v0.x = fmaxf(v0.x, 0.f); v0.y = fmaxf(v0.y, 0.f);
                v1.x = fmaxf(v1.x, 0.f); v1.y = fmaxf(v1.y, 0.f);
            }
            if (r0 < M)     *(float2*)(out + (size_t)r0 * BN + col)       = v0;
            if (r0 + 8 < M) *(float2*)(out + (size_t)(r0 + 8) * BN + col) = v1;
        }
    }
}

// ---------------------------------------------------------------------------
// launch
// ---------------------------------------------------------------------------
extern "C" void kernel_launch(void* const* d_in, const int* in_sizes, int n_in,
                              void* d_out, int out_size) {
    const float* x   = (const float*)d_in[0];
    const int*   src = (const int*)d_in[1];
    const int*   dst = (const int*)d_in[2];
    const float* Ws0 = (const float*)d_in[3];
    const float* Wn0 = (const float*)d_in[4];
    const float* b0  = (const float*)d_in[5];
    const float* Ws1 = (const float*)d_in[6];
    const float* Wn1 = (const float*)d_in[7];
    const float* b1  = (const float*)d_in[8];
    const float* Ws2 = (const float*)d_in[9];
    const float* Wn2 = (const float*)d_in[10];
    const float* b2  = (const float*)d_in[11];
    float* out = (float*)d_out;

    const int M = in_sizes[0] / 128;   // 100000
    const int E = in_sizes[1];         // 1600000

    float *h1, *h2, *agg, *invdeg;
    int *tmpint, *rowstart, *colsrc, *blocksum, *blockoff;
    cudaGetSymbolAddress((void**)&h1,  g_h1);
    cudaGetSymbolAddress((void**)&h2,  g_h2);
    cudaGetSymbolAddress((void**)&agg, g_agg);
    cudaGetSymbolAddress((void**)&invdeg, g_invdeg);
    cudaGetSymbolAddress((void**)&tmpint, g_tmpint);
    cudaGetSymbolAddress((void**)&rowstart, g_rowstart);
    cudaGetSymbolAddress((void**)&colsrc, g_colsrc);
    cudaGetSymbolAddress((void**)&blocksum, g_blocksum);
    cudaGetSymbolAddress((void**)&blockoff, g_blockoff);

    int* degi   = tmpint;
    int* cursor = tmpint + MAXN;

    const int gemmBlocks   = (M + 127) / 128;
    const int edgeBlocks   = (E + 255) / 256;
    const int gatherBlocks = (M * 32 + 255) / 256;
    const int scanBlocks   = (M + 255) / 256;

    // ---- CSR build (dst-sorted) ----
    cudaMemsetAsync(tmpint, 0, (size_t)2 * MAXN * sizeof(int));   // degi + cursor
    count_deg_kernel<<<edgeBlocks, 256>>>(dst, degi, E);
    block_reduce_kernel<<<scanBlocks, 256>>>(degi, blocksum, M);
    scan_blocksums_kernel<<<1, 512>>>(blocksum, blockoff, scanBlocks);
    scan_write_kernel<<<scanBlocks, 256>>>(degi, blockoff, rowstart, invdeg, M);
    fill_kernel<<<edgeBlocks, 256>>>(src, dst, rowstart, cursor, colsrc, E);

    // ---- layer 0 ----
    gather_kernel<<<gatherBlocks, 256>>>(x, rowstart, colsrc, invdeg, agg, M);
    gemm_tc_kernel<128, true><<<gemmBlocks, 256>>>(x, agg, Ws0, Wn0, b0, h1, M);

    // ---- layer 1 ----
    gather_kernel<<<gatherBlocks, 256>>>(h1, rowstart, colsrc, invdeg, agg, M);
    gemm_tc_kernel<128, true><<<gemmBlocks, 256>>>(h1, agg, Ws1, Wn1, b1, h2, M);

    // ---- layer 2 (BN=64, no relu) ----
    gather_kernel<<<gatherBlocks, 256>>>(h2, rowstart, colsrc, invdeg, agg, M);
    gemm_tc_kernel<64, false><<<gemmBlocks, 256>>>(h2, agg, Ws2, Wn2, b2, out, M);
}

// round 10
// speedup vs baseline: 1.5076x; 1.3813x over previous
#include <cuda_runtime.h>
#include <cuda_fp16.h>
#include <cstdint>

// ---------------------------------------------------------------------------
// GraphSAGE, 3 layers, mean aggregation. Aggregate-then-transform:
//   agg = mean_{e: dst=d} h[src_e]          (CSR gather, atomic-free, fp16)
//   h'  = act([h | agg] @ [Wself; Wneigh] + b)   (dual-A fp16 MMA, fp32 accum)
// fp16 mantissa (10 bits) == tf32 mantissa, so this matches the previous
// tf32 pipeline's precision while doubling tensor throughput and halving
// gather traffic. All accumulation is fp32.
// ---------------------------------------------------------------------------

#define MAXN 100000
#define MAXE 1600000

__device__ __half g_x16[(size_t)MAXN * 128];
__device__ __half g_h1[(size_t)MAXN * 128];
__device__ __half g_h2[(size_t)MAXN * 128];
__device__ __half g_agg[(size_t)MAXN * 128];
__device__ __half g_bt0[128 * 256];         // Bt[n][k] (k<128: Ws, else Wn)
__device__ __half g_bt1[128 * 256];
__device__ __half g_bt2[64 * 256];
__device__ float g_invdeg[MAXN];
__device__ int   g_tmpint[2 * MAXN];        // degi | cursor
__device__ int   g_rowstart[MAXN + 1];
__device__ int   g_colsrc[MAXE];
__device__ int   g_blocksum[512];
__device__ int   g_blockoff[512];

// ---------------------------------------------------------------------------
// CSR build
// ---------------------------------------------------------------------------
__global__ void count_deg_kernel(const int* __restrict__ dst, int* __restrict__ degi, int E) {
    int i = blockIdx.x * blockDim.x + threadIdx.x;
    if (i < E) atomicAdd(&degi[dst[i]], 1);
}

__global__ void block_reduce_kernel(const int* __restrict__ degi,
                                    int* __restrict__ blocksum, int N) {
    __shared__ int s[256];
    int t = threadIdx.x;
    int i = blockIdx.x * 256 + t;
    s[t] = (i < N) ? degi[i] : 0;
    __syncthreads();
#pragma unroll
    for (int off = 128; off > 0; off >>= 1) {
        if (t < off) s[t] += s[t + off];
        __syncthreads();
    }
    if (t == 0) blocksum[blockIdx.x] = s[0];
}

__global__ void scan_blocksums_kernel(const int* __restrict__ blocksum,
                                      int* __restrict__ blockoff, int nb) {
    __shared__ int s[512];
    int t = threadIdx.x;
    int v = (t < nb) ? blocksum[t] : 0;
    s[t] = v;
    __syncthreads();
    for (int off = 1; off < 512; off <<= 1) {
        int u = (t >= off) ? s[t - off] : 0;
        __syncthreads();
        s[t] += u;
        __syncthreads();
    }
    if (t < nb) blockoff[t] = s[t] - v;
}

__global__ void scan_write_kernel(const int* __restrict__ degi,
                                  const int* __restrict__ blockoff,
                                  int* __restrict__ rowstart,
                                  float* __restrict__ invdeg, int N) {
    __shared__ int s[256];
    int t = threadIdx.x;
    int i = blockIdx.x * 256 + t;
    int v = (i < N) ? degi[i] : 0;
    s[t] = v;
    __syncthreads();
    for (int off = 1; off < 256; off <<= 1) {
        int u = (t >= off) ? s[t - off] : 0;
        __syncthreads();
        s[t] += u;
        __syncthreads();
    }
    if (i < N) {
        int excl = s[t] - v + blockoff[blockIdx.x];
        rowstart[i] = excl;
        invdeg[i] = 1.0f / fmaxf((float)v, 1.0f);
        if (i == N - 1) rowstart[N] = excl + v;
    }
}

__global__ void fill_kernel(const int* __restrict__ src,
                            const int* __restrict__ dst,
                            const int* __restrict__ rowstart,
                            int* __restrict__ cursor,
                            int* __restrict__ colsrc, int E) {
    int i = blockIdx.x * blockDim.x + threadIdx.x;
    if (i >= E) return;
    int d = dst[i];
    int pos = rowstart[d] + atomicAdd(&cursor[d], 1);
    colsrc[pos] = src[i];
}

// ---------------------------------------------------------------------------
// prep: x -> fp16 ; W pairs -> fp16 transposed [N][256]
// ---------------------------------------------------------------------------
__global__ void prep_x16_kernel(const float* __restrict__ x,
                                __half* __restrict__ x16, int n4) {
    int i = blockIdx.x * blockDim.x + threadIdx.x;   // float4 slots
    if (i >= n4) return;
    float4 v = *(const float4*)(x + (size_t)i * 4);
    __half2 h0 = __floats2half2_rn(v.x, v.y);
    __half2 h1 = __floats2half2_rn(v.z, v.w);
    uint2 u;
    u.x = *(uint32_t*)&h0;
    u.y = *(uint32_t*)&h1;
    *(uint2*)(x16 + (size_t)i * 4) = u;
}

__global__ void prep_bt_kernel(const float* __restrict__ Ws,
                               const float* __restrict__ Wn,
                               __half* __restrict__ Bt, int BN) {
    int i = blockIdx.x * blockDim.x + threadIdx.x;
    if (i >= BN * 256) return;
    int n = i >> 8, k = i & 255;
    float v = (k < 128) ? Ws[k * BN + n] : Wn[(k - 128) * BN + n];
    Bt[n * 256 + k] = __float2half_rn(v);
}

// ---------------------------------------------------------------------------
// gather (fp16): agg[n] = fp16(inv_deg[n] * sum h16[colsrc[j]])   (warp/node)
// lane handles 4 halves (8B); fp32 accumulation.
// ---------------------------------------------------------------------------
__device__ __forceinline__ void acc_u2(float4& a, uint2 u) {
    float2 p0 = __half22float2(*(__half2*)&u.x);
    float2 p1 = __half22float2(*(__half2*)&u.y);
    a.x += p0.x; a.y += p0.y; a.z += p1.x; a.w += p1.y;
}

__global__ void gather_kernel(const __half* __restrict__ h,
                              const int* __restrict__ rowstart,
                              const int* __restrict__ colsrc,
                              const float* __restrict__ invdeg,
                              __half* __restrict__ agg, int N) {
    int warp = (blockIdx.x * blockDim.x + threadIdx.x) >> 5;
    int lane = threadIdx.x & 31;
    if (warp >= N) return;
    int beg = rowstart[warp];
    int end = rowstart[warp + 1];

    const __half* hb = h + lane * 4;
    float4 acc = make_float4(0.f, 0.f, 0.f, 0.f);
    int j = beg;
    for (; j + 4 <= end; j += 4) {
        int s0 = __ldg(colsrc + j + 0);
        int s1 = __ldg(colsrc + j + 1);
        int s2 = __ldg(colsrc + j + 2);
        int s3 = __ldg(colsrc + j + 3);
        uint2 u0 = *(const uint2*)(hb + (size_t)s0 * 128);
        uint2 u1 = *(const uint2*)(hb + (size_t)s1 * 128);
        uint2 u2 = *(const uint2*)(hb + (size_t)s2 * 128);
        uint2 u3 = *(const uint2*)(hb + (size_t)s3 * 128);
        acc_u2(acc, u0); acc_u2(acc, u1); acc_u2(acc, u2); acc_u2(acc, u3);
    }
    for (; j < end; j++) {
        int s = __ldg(colsrc + j);
        uint2 u = *(const uint2*)(hb + (size_t)s * 128);
        acc_u2(acc, u);
    }
    float id = invdeg[warp];
    __half2 o0 = __floats2half2_rn(acc.x * id, acc.y * id);
    __half2 o1 = __floats2half2_rn(acc.z * id, acc.w * id);
    uint2 o;
    o.x = *(uint32_t*)&o0;
    o.y = *(uint32_t*)&o1;
    *(uint2*)(agg + (size_t)warp * 128 + lane * 4) = o;
}

// ---------------------------------------------------------------------------
// fp16 MMA helper: m16n8k16, fp32 accumulate
// ---------------------------------------------------------------------------
__device__ __forceinline__ void mma_f16(float& c0, float& c1, float& c2, float& c3,
                                        uint32_t a0, uint32_t a1, uint32_t a2, uint32_t a3,
                                        uint32_t b0, uint32_t b1) {
    asm volatile(
        "mma.sync.aligned.m16n8k16.row.col.f32.f16.f16.f32 "
        "{%0,%1,%2,%3}, {%4,%5,%6,%7}, {%8,%9}, {%0,%1,%2,%3};\n"
        : "+f"(c0), "+f"(c1), "+f"(c2), "+f"(c3)
        : "r"(a0), "r"(a1), "r"(a2), "r"(a3), "r"(b0), "r"(b1));
}

// ---------------------------------------------------------------------------
// dual-A fp16 GEMM: out[M,BN] = A1[M,128]@W1 + A2[M,128]@W2 + b   (K=256)
// A1,A2,Bt fp16; Bt pre-transposed [N][256] (k-contiguous per n).
// Block 128 x BN, 256 threads = 8 warps (4m x 2n), warp tile 32 x BN/2.
// K staged at KT=32 halves, double-buffered, register prefetch.
// smem rows padded to stride 40 halves (80B) -> conflict-free frag reads.
// ---------------------------------------------------------------------------
template <int BN, bool RELU, bool OUTHALF>
__launch_bounds__(256, 2)
__global__ void gemm_f16_kernel(const __half* __restrict__ A1,
                                const __half* __restrict__ A2,
                                const __half* __restrict__ Bt,
                                const float* __restrict__ bias,
                                void* __restrict__ outv, int M) {
    constexpr int KT = 32;             // halves per stage
    constexpr int NS = 8;              // 256 / KT
    constexpr int ST = 40;             // smem row stride in halves (80 B)
    constexpr int NF = BN / 16;        // n-frags per warp
    constexpr int NBU = BN * 8 / 256;  // B uint2 loads / thread / stage (4 or 2)

    __shared__ __align__(16) __half As[2][128 * ST];
    __shared__ __align__(16) __half Bs[2][BN * ST];

    const int tid  = threadIdx.x;
    const int wid  = tid >> 5;
    const int lane = tid & 31;
    const int g    = lane >> 2;        // 0..7
    const int t4   = lane & 3;         // 0..3
    const int warpM = wid & 3;
    const int warpN = wid >> 2;
    const int rowBase = blockIdx.x * 128;

    float acc[2][NF][4];
#pragma unroll
    for (int mf = 0; mf < 2; mf++)
#pragma unroll
        for (int nf = 0; nf < NF; nf++)
#pragma unroll
            for (int r = 0; r < 4; r++) acc[mf][nf][r] = 0.f;

    uint2 ra[4];
    uint2 rb[NBU];

    // ---- prologue: stage 0 (A1, k0=0) ----
    {
#pragma unroll
        for (int i = 0; i < 4; i++) {
            int f = tid + i * 256;         // 1024 uint2 slots (128 rows x 8)
            int r = f >> 3, q = f & 7;
            int row = rowBase + r;
            uint2 v = make_uint2(0u, 0u);
            if (row < M) v = *(const uint2*)(A1 + (size_t)row * 128 + q * 4);
            *(uint2*)&As[0][r * ST + q * 4] = v;
        }
#pragma unroll
        for (int i = 0; i < NBU; i++) {
            int f = tid + i * 256;
            int n = f >> 3, q = f & 7;
            uint2 v = *(const uint2*)(Bt + (size_t)n * 256 + q * 4);
            *(uint2*)&Bs[0][n * ST + q * 4] = v;
        }
    }
    __syncthreads();

    // ---- main loop ----
#pragma unroll 1
    for (int s = 0; s < NS; s++) {
        const int buf = s & 1;

        if (s + 1 < NS) {
            const __half* A = (s + 1 < 4) ? A1 : A2;
            const int k0 = ((s + 1) & 3) * KT;
#pragma unroll
            for (int i = 0; i < 4; i++) {
                int f = tid + i * 256;
                int r = f >> 3, q = f & 7;
                int row = rowBase + r;
                ra[i] = make_uint2(0u, 0u);
                if (row < M) ra[i] = *(const uint2*)(A + (size_t)row * 128 + k0 + q * 4);
            }
            const int kb0 = (s + 1) * KT;
#pragma unroll
            for (int i = 0; i < NBU; i++) {
                int f = tid + i * 256;
                int n = f >> 3, q = f & 7;
                rb[i] = *(const uint2*)(Bt + (size_t)n * 256 + kb0 + q * 4);
            }
        }

        // compute: 2 k16-steps on buf
#pragma unroll
        for (int k16 = 0; k16 < 2; k16++) {
            const int kb = k16 * 16;
            uint32_t a[2][4];
#pragma unroll
            for (int mf = 0; mf < 2; mf++) {
                int r0 = warpM * 32 + mf * 16 + g;
                const __half* p0 = &As[buf][r0 * ST + kb + 2 * t4];
                const __half* p1 = &As[buf][(r0 + 8) * ST + kb + 2 * t4];
                a[mf][0] = *(const uint32_t*)(p0);
                a[mf][1] = *(const uint32_t*)(p1);
                a[mf][2] = *(const uint32_t*)(p0 + 8);
                a[mf][3] = *(const uint32_t*)(p1 + 8);
            }
#pragma unroll
            for (int nf = 0; nf < NF; nf++) {
                int cb = warpN * (BN / 2) + nf * 8 + g;
                const __half* pb = &Bs[buf][cb * ST + kb + 2 * t4];
                uint32_t b0 = *(const uint32_t*)(pb);
                uint32_t b1 = *(const uint32_t*)(pb + 8);
#pragma unroll
                for (int mf = 0; mf < 2; mf++) {
                    mma_f16(acc[mf][nf][0], acc[mf][nf][1],
                            acc[mf][nf][2], acc[mf][nf][3],
                            a[mf][0], a[mf][1], a[mf][2], a[mf][3], b0, b1);
                }
            }
        }

        if (s + 1 < NS) {
            const int nbuf = buf ^ 1;
#pragma unroll
            for (int i = 0; i < 4; i++) {
                int f = tid + i * 256;
                int r = f >> 3, q = f & 7;
                *(uint2*)&As[nbuf][r * ST + q * 4] = ra[i];
            }
#pragma unroll
            for (int i = 0; i < NBU; i++) {
                int f = tid + i * 256;
                int n = f >> 3, q = f & 7;
                *(uint2*)&Bs[nbuf][n * ST + q * 4] = rb[i];
            }
            __syncthreads();
        }
    }

    // ---- epilogue: bias (+relu); write fp16 (hidden) or fp32 (final) ----
#pragma unroll
    for (int nf = 0; nf < NF; nf++) {
        int col = warpN * (BN / 2) + nf * 8 + t4 * 2;
        float2 bv = *(const float2*)(bias + col);
#pragma unroll
        for (int mf = 0; mf < 2; mf++) {
            int r0 = rowBase + warpM * 32 + mf * 16 + g;
            float2 v0 = make_float2(acc[mf][nf][0] + bv.x, acc[mf][nf][1] + bv.y);
            float2 v1 = make_float2(acc[mf][nf][2] + bv.x, acc[mf][nf][3] + bv.y);
            if (RELU) {
                v0.x = fmaxf(v0.x, 0.f); v0.y = fmaxf(v0.y, 0.f);
                v1.x = fmaxf(v1.x, 0.f); v1.y = fmaxf(v1.y, 0.f);
            }
            if (OUTHALF) {
                __half* out = (__half*)outv;
                if (r0 < M) {
                    __half2 hh = __floats2half2_rn(v0.x, v0.y);
                    *(__half2*)(out + (size_t)r0 * BN + col) = hh;
                }
                if (r0 + 8 < M) {
                    __half2 hh = __floats2half2_rn(v1.x, v1.y);
                    *(__half2*)(out + (size_t)(r0 + 8) * BN + col) = hh;
                }
            } else {
                float* out = (float*)outv;
                if (r0 < M)     *(float2*)(out + (size_t)r0 * BN + col)       = v0;
                if (r0 + 8 < M) *(float2*)(out + (size_t)(r0 + 8) * BN + col) = v1;
            }
        }
    }
}

// ---------------------------------------------------------------------------
// launch
// ---------------------------------------------------------------------------
extern "C" void kernel_launch(void* const* d_in, const int* in_sizes, int n_in,
                              void* d_out, int out_size) {
    const float* x   = (const float*)d_in[0];
    const int*   src = (const int*)d_in[1];
    const int*   dst = (const int*)d_in[2];
    const float* Ws0 = (const float*)d_in[3];
    const float* Wn0 = (const float*)d_in[4];
    const float* b0  = (const float*)d_in[5];
    const float* Ws1 = (const float*)d_in[6];
    const float* Wn1 = (const float*)d_in[7];
    const float* b1  = (const float*)d_in[8];
    const float* Ws2 = (const float*)d_in[9];
    const float* Wn2 = (const float*)d_in[10];
    const float* b2  = (const float*)d_in[11];
    float* out = (float*)d_out;

    const int M = in_sizes[0] / 128;   // 100000
    const int E = in_sizes[1];         // 1600000

    __half *x16, *h1, *h2, *agg, *bt0, *bt1, *bt2;
    float *invdeg;
    int *tmpint, *rowstart, *colsrc, *blocksum, *blockoff;
    cudaGetSymbolAddress((void**)&x16, g_x16);
    cudaGetSymbolAddress((void**)&h1,  g_h1);
    cudaGetSymbolAddress((void**)&h2,  g_h2);
    cudaGetSymbolAddress((void**)&agg, g_agg);
    cudaGetSymbolAddress((void**)&bt0, g_bt0);
    cudaGetSymbolAddress((void**)&bt1, g_bt1);
    cudaGetSymbolAddress((void**)&bt2, g_bt2);
    cudaGetSymbolAddress((void**)&invdeg, g_invdeg);
    cudaGetSymbolAddress((void**)&tmpint, g_tmpint);
    cudaGetSymbolAddress((void**)&rowstart, g_rowstart);
    cudaGetSymbolAddress((void**)&colsrc, g_colsrc);
    cudaGetSymbolAddress((void**)&blocksum, g_blocksum);
    cudaGetSymbolAddress((void**)&blockoff, g_blockoff);

    int* degi   = tmpint;
    int* cursor = tmpint + MAXN;

    const int gemmBlocks   = (M + 127) / 128;
    const int edgeBlocks   = (E + 255) / 256;
    const int gatherBlocks = (M * 32 + 255) / 256;
    const int scanBlocks   = (M + 255) / 256;

    // ---- prep (independent of CSR) ----
    prep_x16_kernel<<<(M * 32 + 255) / 256, 256>>>(x, x16, M * 32);
    prep_bt_kernel<<<(128 * 256 + 255) / 256, 256>>>(Ws0, Wn0, bt0, 128);
    prep_bt_kernel<<<(128 * 256 + 255) / 256, 256>>>(Ws1, Wn1, bt1, 128);
    prep_bt_kernel<<<(64 * 256 + 255) / 256, 256>>>(Ws2, Wn2, bt2, 64);

    // ---- CSR build (dst-sorted) ----
    cudaMemsetAsync(tmpint, 0, (size_t)2 * MAXN * sizeof(int));
    count_deg_kernel<<<edgeBlocks, 256>>>(dst, degi, E);
    block_reduce_kernel<<<scanBlocks, 256>>>(degi, blocksum, M);
    scan_blocksums_kernel<<<1, 512>>>(blocksum, blockoff, scanBlocks);
    scan_write_kernel<<<scanBlocks, 256>>>(degi, blockoff, rowstart, invdeg, M);
    fill_kernel<<<edgeBlocks, 256>>>(src, dst, rowstart, cursor, colsrc, E);

    // ---- layer 0: h1 = relu(x@Ws0 + agg(x)@Wn0 + b0) ----
    gather_kernel<<<gatherBlocks, 256>>>(x16, rowstart, colsrc, invdeg, agg, M);
    gemm_f16_kernel<128, true, true><<<gemmBlocks, 256>>>(x16, agg, bt0, b0, h1, M);

    // ---- layer 1 ----
    gather_kernel<<<gatherBlocks, 256>>>(h1, rowstart, colsrc, invdeg, agg, M);
    gemm_f16_kernel<128, true, true><<<gemmBlocks, 256>>>(h1, agg, bt1, b1, h2, M);

    // ---- layer 2 (BN=64, no relu, fp32 out) ----
    gather_kernel<<<gatherBlocks, 256>>>(h2, rowstart, colsrc, invdeg, agg, M);
    gemm_f16_kernel<64, false, false><<<gemmBlocks, 256>>>(h2, agg, bt2, b2, out, M);
}

// round 11
// speedup vs baseline: 1.6317x; 1.0824x over previous
#include <cuda_runtime.h>
#include <cuda_fp16.h>
#include <cstdint>

// ---------------------------------------------------------------------------
// GraphSAGE, 3 layers, mean aggregation, fp16 data / fp32 accumulation.
//   agg = mean_{e: dst=d} h[src_e]          (CSR gather, atomic-free)
//   h'  = act([h | agg] @ [Wself; Wneigh] + b)   (dual-A fp16 MMA, K=256)
// ---------------------------------------------------------------------------

#define MAXN 100000
#define MAXE 1600000

__device__ __half g_x16[(size_t)MAXN * 128];
__device__ __half g_h1[(size_t)MAXN * 128];
__device__ __half g_h2[(size_t)MAXN * 128];
__device__ __half g_agg[(size_t)MAXN * 128];
__device__ __half g_bt0[128 * 256];         // Bt[n][k] (k<128: Ws, else Wn)
__device__ __half g_bt1[128 * 256];
__device__ __half g_bt2[64 * 256];
__device__ float g_invdeg[MAXN];
__device__ int   g_tmpint[2 * MAXN];        // degi | cursor
__device__ int   g_rowstart[MAXN + 1];
__device__ int   g_colsrc[MAXE];
__device__ int   g_blocksum[512];

// ---------------------------------------------------------------------------
// CSR build
// ---------------------------------------------------------------------------
__global__ void count_deg_kernel(const int* __restrict__ dst, int* __restrict__ degi, int E) {
    int i = blockIdx.x * blockDim.x + threadIdx.x;
    if (i < E) atomicAdd(&degi[dst[i]], 1);
}

__global__ void block_reduce_kernel(const int* __restrict__ degi,
                                    int* __restrict__ blocksum, int N) {
    __shared__ int s[256];
    int t = threadIdx.x;
    int i = blockIdx.x * 256 + t;
    s[t] = (i < N) ? degi[i] : 0;
    __syncthreads();
#pragma unroll
    for (int off = 128; off > 0; off >>= 1) {
        if (t < off) s[t] += s[t + off];
        __syncthreads();
    }
    if (t == 0) blocksum[blockIdx.x] = s[0];
}

// per-block scan + self-computed global offset -> rowstart, invdeg
__global__ void scan_write_kernel(const int* __restrict__ degi,
                                  const int* __restrict__ blocksum,
                                  int* __restrict__ rowstart,
                                  float* __restrict__ invdeg, int N) {
    __shared__ int red[256];
    __shared__ int s[256];
    int t = threadIdx.x;

    // block offset = sum of blocksum[0 .. blockIdx.x)
    int partial = 0;
    for (int b = t; b < blockIdx.x; b += 256) partial += blocksum[b];
    red[t] = partial;
    __syncthreads();
#pragma unroll
    for (int off = 128; off > 0; off >>= 1) {
        if (t < off) red[t] += red[t + off];
        __syncthreads();
    }
    const int blockoff = red[0];

    int i = blockIdx.x * 256 + t;
    int v = (i < N) ? degi[i] : 0;
    s[t] = v;
    __syncthreads();
    for (int off = 1; off < 256; off <<= 1) {
        int u = (t >= off) ? s[t - off] : 0;
        __syncthreads();
        s[t] += u;
        __syncthreads();
    }
    if (i < N) {
        int excl = s[t] - v + blockoff;
        rowstart[i] = excl;
        invdeg[i] = 1.0f / fmaxf((float)v, 1.0f);
        if (i == N - 1) rowstart[N] = excl + v;
    }
}

__global__ void fill_kernel(const int* __restrict__ src,
                            const int* __restrict__ dst,
                            const int* __restrict__ rowstart,
                            int* __restrict__ cursor,
                            int* __restrict__ colsrc, int E) {
    int i = blockIdx.x * blockDim.x + threadIdx.x;
    if (i >= E) return;
    int d = dst[i];
    int pos = rowstart[d] + atomicAdd(&cursor[d], 1);
    colsrc[pos] = src[i];
}

// ---------------------------------------------------------------------------
// merged prep: x -> fp16, plus 3 transposed fp16 weight blocks
// block ranges: [0, NXB)           -> x16
//               [NXB, NXB+128)     -> bt0
//               [NXB+128, NXB+256) -> bt1
//               [NXB+256, NXB+320) -> bt2
// ---------------------------------------------------------------------------
__global__ void prep_all_kernel(const float* __restrict__ x, __half* __restrict__ x16, int n4,
                                const float* __restrict__ Ws0, const float* __restrict__ Wn0,
                                __half* __restrict__ bt0,
                                const float* __restrict__ Ws1, const float* __restrict__ Wn1,
                                __half* __restrict__ bt1,
                                const float* __restrict__ Ws2, const float* __restrict__ Wn2,
                                __half* __restrict__ bt2,
                                int NXB) {
    int b = blockIdx.x;
    if (b < NXB) {
        int i = b * 256 + threadIdx.x;          // float4 slots
        if (i >= n4) return;
        float4 v = *(const float4*)(x + (size_t)i * 4);
        __half2 h0 = __floats2half2_rn(v.x, v.y);
        __half2 h1 = __floats2half2_rn(v.z, v.w);
        uint2 u;
        u.x = *(uint32_t*)&h0;
        u.y = *(uint32_t*)&h1;
        *(uint2*)(x16 + (size_t)i * 4) = u;
        return;
    }
    b -= NXB;
    const float* Ws;
    const float* Wn;
    __half* Bt;
    int BN;
    if (b < 128)      { Ws = Ws0; Wn = Wn0; Bt = bt0; BN = 128; }
    else if (b < 256) { Ws = Ws1; Wn = Wn1; Bt = bt1; BN = 128; b -= 128; }
    else              { Ws = Ws2; Wn = Wn2; Bt = bt2; BN = 64;  b -= 256; }
    int i = b * 256 + threadIdx.x;
    if (i >= BN * 256) return;
    int n = i >> 8, k = i & 255;
    float v = (k < 128) ? Ws[k * BN + n] : Wn[(k - 128) * BN + n];
    Bt[n * 256 + k] = __float2half_rn(v);
}

// ---------------------------------------------------------------------------
// gather: 16 lanes per node (uint4 = 8 halves / lane), 2 nodes per warp,
// 4-deep edge unroll -> 8 row-loads in flight per warp. fp32 accumulation.
// ---------------------------------------------------------------------------
__device__ __forceinline__ void acc_u4(float* a, uint4 u) {
    float2 p0 = __half22float2(*(__half2*)&u.x);
    float2 p1 = __half22float2(*(__half2*)&u.y);
    float2 p2 = __half22float2(*(__half2*)&u.z);
    float2 p3 = __half22float2(*(__half2*)&u.w);
    a[0] += p0.x; a[1] += p0.y; a[2] += p1.x; a[3] += p1.y;
    a[4] += p2.x; a[5] += p2.y; a[6] += p3.x; a[7] += p3.y;
}

__global__ void gather_kernel(const __half* __restrict__ h,
                              const int* __restrict__ rowstart,
                              const int* __restrict__ colsrc,
                              const float* __restrict__ invdeg,
                              __half* __restrict__ agg, int N) {
    int node   = (blockIdx.x * blockDim.x + threadIdx.x) >> 4;
    int lane16 = threadIdx.x & 15;
    if (node >= N) return;
    int beg = rowstart[node];
    int end = rowstart[node + 1];

    const __half* hb = h + lane16 * 8;
    float acc[8];
#pragma unroll
    for (int i = 0; i < 8; i++) acc[i] = 0.f;

    int j = beg;
    for (; j + 4 <= end; j += 4) {
        int s0 = __ldg(colsrc + j + 0);
        int s1 = __ldg(colsrc + j + 1);
        int s2 = __ldg(colsrc + j + 2);
        int s3 = __ldg(colsrc + j + 3);
        uint4 u0 = *(const uint4*)(hb + (size_t)s0 * 128);
        uint4 u1 = *(const uint4*)(hb + (size_t)s1 * 128);
        uint4 u2 = *(const uint4*)(hb + (size_t)s2 * 128);
        uint4 u3 = *(const uint4*)(hb + (size_t)s3 * 128);
        acc_u4(acc, u0); acc_u4(acc, u1); acc_u4(acc, u2); acc_u4(acc, u3);
    }
    for (; j < end; j++) {
        int s = __ldg(colsrc + j);
        uint4 u = *(const uint4*)(hb + (size_t)s * 128);
        acc_u4(acc, u);
    }
    float id = invdeg[node];
    __half2 o0 = __floats2half2_rn(acc[0] * id, acc[1] * id);
    __half2 o1 = __floats2half2_rn(acc[2] * id, acc[3] * id);
    __half2 o2 = __floats2half2_rn(acc[4] * id, acc[5] * id);
    __half2 o3 = __floats2half2_rn(acc[6] * id, acc[7] * id);
    uint4 o;
    o.x = *(uint32_t*)&o0; o.y = *(uint32_t*)&o1;
    o.z = *(uint32_t*)&o2; o.w = *(uint32_t*)&o3;
    *(uint4*)(agg + (size_t)node * 128 + lane16 * 8) = o;
}

// ---------------------------------------------------------------------------
// fp16 MMA helper: m16n8k16, fp32 accumulate
// ---------------------------------------------------------------------------
__device__ __forceinline__ void mma_f16(float& c0, float& c1, float& c2, float& c3,
                                        uint32_t a0, uint32_t a1, uint32_t a2, uint32_t a3,
                                        uint32_t b0, uint32_t b1) {
    asm volatile(
        "mma.sync.aligned.m16n8k16.row.col.f32.f16.f16.f32 "
        "{%0,%1,%2,%3}, {%4,%5,%6,%7}, {%8,%9}, {%0,%1,%2,%3};\n"
        : "+f"(c0), "+f"(c1), "+f"(c2), "+f"(c3)
        : "r"(a0), "r"(a1), "r"(a2), "r"(a3), "r"(b0), "r"(b1));
}

// ---------------------------------------------------------------------------
// dual-A fp16 GEMM: out[M,BN] = A1[M,128]@W1 + A2[M,128]@W2 + b   (K=256)
// Block 128 x BN, 256 threads = 8 warps (4m x 2n), warp tile 32 x BN/2.
// K staged at KT=32 halves, double-buffered, register prefetch.
// ---------------------------------------------------------------------------
template <int BN, bool RELU, bool OUTHALF>
__launch_bounds__(256, 2)
__global__ void gemm_f16_kernel(const __half* __restrict__ A1,
                                const __half* __restrict__ A2,
                                const __half* __restrict__ Bt,
                                const float* __restrict__ bias,
                                void* __restrict__ outv, int M) {
    constexpr int KT = 32;
    constexpr int NS = 8;
    constexpr int ST = 40;             // smem row stride in halves (80 B)
    constexpr int NF = BN / 16;
    constexpr int NBU = BN * 8 / 256;

    __shared__ __align__(16) __half As[2][128 * ST];
    __shared__ __align__(16) __half Bs[2][BN * ST];

    const int tid  = threadIdx.x;
    const int wid  = tid >> 5;
    const int lane = tid & 31;
    const int g    = lane >> 2;
    const int t4   = lane & 3;
    const int warpM = wid & 3;
    const int warpN = wid >> 2;
    const int rowBase = blockIdx.x * 128;

    float acc[2][NF][4];
#pragma unroll
    for (int mf = 0; mf < 2; mf++)
#pragma unroll
        for (int nf = 0; nf < NF; nf++)
#pragma unroll
            for (int r = 0; r < 4; r++) acc[mf][nf][r] = 0.f;

    uint2 ra[4];
    uint2 rb[NBU];

    // ---- prologue: stage 0 ----
    {
#pragma unroll
        for (int i = 0; i < 4; i++) {
            int f = tid + i * 256;
            int r = f >> 3, q = f & 7;
            int row = rowBase + r;
            uint2 v = make_uint2(0u, 0u);
            if (row < M) v = *(const uint2*)(A1 + (size_t)row * 128 + q * 4);
            *(uint2*)&As[0][r * ST + q * 4] = v;
        }
#pragma unroll
        for (int i = 0; i < NBU; i++) {
            int f = tid + i * 256;
            int n = f >> 3, q = f & 7;
            uint2 v = *(const uint2*)(Bt + (size_t)n * 256 + q * 4);
            *(uint2*)&Bs[0][n * ST + q * 4] = v;
        }
    }
    __syncthreads();

    // ---- main loop ----
#pragma unroll 1
    for (int s = 0; s < NS; s++) {
        const int buf = s & 1;

        if (s + 1 < NS) {
            const __half* A = (s + 1 < 4) ? A1 : A2;
            const int k0 = ((s + 1) & 3) * KT;
#pragma unroll
            for (int i = 0; i < 4; i++) {
                int f = tid + i * 256;
                int r = f >> 3, q = f & 7;
                int row = rowBase + r;
                ra[i] = make_uint2(0u, 0u);
                if (row < M) ra[i] = *(const uint2*)(A + (size_t)row * 128 + k0 + q * 4);
            }
            const int kb0 = (s + 1) * KT;
#pragma unroll
            for (int i = 0; i < NBU; i++) {
                int f = tid + i * 256;
                int n = f >> 3, q = f & 7;
                rb[i] = *(const uint2*)(Bt + (size_t)n * 256 + kb0 + q * 4);
            }
        }

#pragma unroll
        for (int k16 = 0; k16 < 2; k16++) {
            const int kb = k16 * 16;
            uint32_t a[2][4];
#pragma unroll
            for (int mf = 0; mf < 2; mf++) {
                int r0 = warpM * 32 + mf * 16 + g;
                const __half* p0 = &As[buf][r0 * ST + kb + 2 * t4];
                const __half* p1 = &As[buf][(r0 + 8) * ST + kb + 2 * t4];
                a[mf][0] = *(const uint32_t*)(p0);
                a[mf][1] = *(const uint32_t*)(p1);
                a[mf][2] = *(const uint32_t*)(p0 + 8);
                a[mf][3] = *(const uint32_t*)(p1 + 8);
            }
#pragma unroll
            for (int nf = 0; nf < NF; nf++) {
                int cb = warpN * (BN / 2) + nf * 8 + g;
                const __half* pb = &Bs[buf][cb * ST + kb + 2 * t4];
                uint32_t b0 = *(const uint32_t*)(pb);
                uint32_t b1 = *(const uint32_t*)(pb + 8);
#pragma unroll
                for (int mf = 0; mf < 2; mf++) {
                    mma_f16(acc[mf][nf][0], acc[mf][nf][1],
                            acc[mf][nf][2], acc[mf][nf][3],
                            a[mf][0], a[mf][1], a[mf][2], a[mf][3], b0, b1);
                }
            }
        }

        if (s + 1 < NS) {
            const int nbuf = buf ^ 1;
#pragma unroll
            for (int i = 0; i < 4; i++) {
                int f = tid + i * 256;
                int r = f >> 3, q = f & 7;
                *(uint2*)&As[nbuf][r * ST + q * 4] = ra[i];
            }
#pragma unroll
            for (int i = 0; i < NBU; i++) {
                int f = tid + i * 256;
                int n = f >> 3, q = f & 7;
                *(uint2*)&Bs[nbuf][n * ST + q * 4] = rb[i];
            }
            __syncthreads();
        }
    }

    // ---- epilogue ----
#pragma unroll
    for (int nf = 0; nf < NF; nf++) {
        int col = warpN * (BN / 2) + nf * 8 + t4 * 2;
        float2 bv = *(const float2*)(bias + col);
#pragma unroll
        for (int mf = 0; mf < 2; mf++) {
            int r0 = rowBase + warpM * 32 + mf * 16 + g;
            float2 v0 = make_float2(acc[mf][nf][0] + bv.x, acc[mf][nf][1] + bv.y);
            float2 v1 = make_float2(acc[mf][nf][2] + bv.x, acc[mf][nf][3] + bv.y);
            if (RELU) {
                v0.x = fmaxf(v0.x, 0.f); v0.y = fmaxf(v0.y, 0.f);
                v1.x = fmaxf(v1.x, 0.f); v1.y = fmaxf(v1.y, 0.f);
            }
            if (OUTHALF) {
                __half* out = (__half*)outv;
                if (r0 < M) {
                    __half2 hh = __floats2half2_rn(v0.x, v0.y);
                    *(__half2*)(out + (size_t)r0 * BN + col) = hh;
                }
                if (r0 + 8 < M) {
                    __half2 hh = __floats2half2_rn(v1.x, v1.y);
                    *(__half2*)(out + (size_t)(r0 + 8) * BN + col) = hh;
                }
            } else {
                float* out = (float*)outv;
                if (r0 < M)     *(float2*)(out + (size_t)r0 * BN + col)       = v0;
                if (r0 + 8 < M) *(float2*)(out + (size_t)(r0 + 8) * BN + col) = v1;
            }
        }
    }
}

// ---------------------------------------------------------------------------
// launch
// ---------------------------------------------------------------------------
extern "C" void kernel_launch(void* const* d_in, const int* in_sizes, int n_in,
                              void* d_out, int out_size) {
    const float* x   = (const float*)d_in[0];
    const int*   src = (const int*)d_in[1];
    const int*   dst = (const int*)d_in[2];
    const float* Ws0 = (const float*)d_in[3];
    const float* Wn0 = (const float*)d_in[4];
    const float* b0  = (const float*)d_in[5];
    const float* Ws1 = (const float*)d_in[6];
    const float* Wn1 = (const float*)d_in[7];
    const float* b1  = (const float*)d_in[8];
    const float* Ws2 = (const float*)d_in[9];
    const float* Wn2 = (const float*)d_in[10];
    const float* b2  = (const float*)d_in[11];
    float* out = (float*)d_out;

    const int M = in_sizes[0] / 128;   // 100000
    const int E = in_sizes[1];         // 1600000

    __half *x16, *h1, *h2, *agg, *bt0, *bt1, *bt2;
    float *invdeg;
    int *tmpint, *rowstart, *colsrc, *blocksum;
    cudaGetSymbolAddress((void**)&x16, g_x16);
    cudaGetSymbolAddress((void**)&h1,  g_h1);
    cudaGetSymbolAddress((void**)&h2,  g_h2);
    cudaGetSymbolAddress((void**)&agg, g_agg);
    cudaGetSymbolAddress((void**)&bt0, g_bt0);
    cudaGetSymbolAddress((void**)&bt1, g_bt1);
    cudaGetSymbolAddress((void**)&bt2, g_bt2);
    cudaGetSymbolAddress((void**)&invdeg, g_invdeg);
    cudaGetSymbolAddress((void**)&tmpint, g_tmpint);
    cudaGetSymbolAddress((void**)&rowstart, g_rowstart);
    cudaGetSymbolAddress((void**)&colsrc, g_colsrc);
    cudaGetSymbolAddress((void**)&blocksum, g_blocksum);

    int* degi   = tmpint;
    int* cursor = tmpint + MAXN;

    const int gemmBlocks   = (M + 127) / 128;
    const int edgeBlocks   = (E + 255) / 256;
    const int gatherBlocks = (M * 16 + 255) / 256;   // 16 lanes per node
    const int scanBlocks   = (M + 255) / 256;
    const int NXB          = (M * 32 + 255) / 256;   // x16 float4-slot blocks

    // ---- merged prep (x -> fp16, weights -> fp16 transposed) ----
    prep_all_kernel<<<NXB + 320, 256>>>(x, x16, M * 32,
                                        Ws0, Wn0, bt0,
                                        Ws1, Wn1, bt1,
                                        Ws2, Wn2, bt2, NXB);

    // ---- CSR build (dst-sorted) ----
    cudaMemsetAsync(tmpint, 0, (size_t)2 * MAXN * sizeof(int));
    count_deg_kernel<<<edgeBlocks, 256>>>(dst, degi, E);
    block_reduce_kernel<<<scanBlocks, 256>>>(degi, blocksum, M);
    scan_write_kernel<<<scanBlocks, 256>>>(degi, blocksum, rowstart, invdeg, M);
    fill_kernel<<<edgeBlocks, 256>>>(src, dst, rowstart, cursor, colsrc, E);

    // ---- layer 0: h1 = relu(x@Ws0 + agg(x)@Wn0 + b0) ----
    gather_kernel<<<gatherBlocks, 256>>>(x16, rowstart, colsrc, invdeg, agg, M);
    gemm_f16_kernel<128, true, true><<<gemmBlocks, 256>>>(x16, agg, bt0, b0, h1, M);

    // ---- layer 1 ----
    gather_kernel<<<gatherBlocks, 256>>>(h1, rowstart, colsrc, invdeg, agg, M);
    gemm_f16_kernel<128, true, true><<<gemmBlocks, 256>>>(h1, agg, bt1, b1, h2, M);

    // ---- layer 2 (BN=64, no relu, fp32 out) ----
    gather_kernel<<<gatherBlocks, 256>>>(h2, rowstart, colsrc, invdeg, agg, M);
    gemm_f16_kernel<64, false, false><<<gemmBlocks, 256>>>(h2, agg, bt2, b2, out, M);
}

// round 12
// speedup vs baseline: 1.6674x; 1.0219x over previous
#include <cuda_runtime.h>
#include <cuda_fp16.h>
#include <cstdint>

// ---------------------------------------------------------------------------
// GraphSAGE, 3 layers, mean aggregation, fp16 data / fp32 accumulation.
// Layers 0/1: agg = mean h[src]; h' = relu([h|agg] @ [Ws;Wn] + b)  (dual-A)
// Layer 2 (transform-first, 64-wide gather):
//   y2 = h2 @ Wn2 ; G = mean y2[src] ; out = h2 @ Ws2 + G + b2
// ---------------------------------------------------------------------------

#define MAXN 100000
#define MAXE 1600000

__device__ __half g_x16[(size_t)MAXN * 128];
__device__ __half g_h1[(size_t)MAXN * 128];
__device__ __half g_h2[(size_t)MAXN * 128];
__device__ __half g_agg[(size_t)MAXN * 128];   // also y2 / G (64-wide) reuse
__device__ __half g_y2[(size_t)MAXN * 64];
__device__ __half g_bt0[128 * 256];            // [n][k]: k<128 Ws, else Wn
__device__ __half g_bt1[128 * 256];
__device__ __half g_bts2[64 * 128];            // Ws2^T
__device__ __half g_btn2[64 * 128];            // Wn2^T
__device__ float g_invdeg[MAXN];
__device__ int   g_tmpint[2 * MAXN];           // degi | cursor
__device__ int   g_rowstart[MAXN + 1];
__device__ int   g_colsrc[MAXE];
__device__ int   g_blocksum[512];

// ---------------------------------------------------------------------------
// CSR build
// ---------------------------------------------------------------------------
__global__ void count_deg_kernel(const int* __restrict__ dst, int* __restrict__ degi, int E) {
    int i = blockIdx.x * blockDim.x + threadIdx.x;
    if (i < E) atomicAdd(&degi[dst[i]], 1);
}

__global__ void block_reduce_kernel(const int* __restrict__ degi,
                                    int* __restrict__ blocksum, int N) {
    __shared__ int s[256];
    int t = threadIdx.x;
    int i = blockIdx.x * 256 + t;
    s[t] = (i < N) ? degi[i] : 0;
    __syncthreads();
#pragma unroll
    for (int off = 128; off > 0; off >>= 1) {
        if (t < off) s[t] += s[t + off];
        __syncthreads();
    }
    if (t == 0) blocksum[blockIdx.x] = s[0];
}

__global__ void scan_write_kernel(const int* __restrict__ degi,
                                  const int* __restrict__ blocksum,
                                  int* __restrict__ rowstart,
                                  float* __restrict__ invdeg, int N) {
    __shared__ int red[256];
    __shared__ int s[256];
    int t = threadIdx.x;

    int partial = 0;
    for (int b = t; b < blockIdx.x; b += 256) partial += blocksum[b];
    red[t] = partial;
    __syncthreads();
#pragma unroll
    for (int off = 128; off > 0; off >>= 1) {
        if (t < off) red[t] += red[t + off];
        __syncthreads();
    }
    const int blockoff = red[0];

    int i = blockIdx.x * 256 + t;
    int v = (i < N) ? degi[i] : 0;
    s[t] = v;
    __syncthreads();
    for (int off = 1; off < 256; off <<= 1) {
        int u = (t >= off) ? s[t - off] : 0;
        __syncthreads();
        s[t] += u;
        __syncthreads();
    }
    if (i < N) {
        int excl = s[t] - v + blockoff;
        rowstart[i] = excl;
        invdeg[i] = 1.0f / fmaxf((float)v, 1.0f);
        if (i == N - 1) rowstart[N] = excl + v;
    }
}

__global__ void fill_kernel(const int* __restrict__ src,
                            const int* __restrict__ dst,
                            const int* __restrict__ rowstart,
                            int* __restrict__ cursor,
                            int* __restrict__ colsrc, int E) {
    int i = blockIdx.x * blockDim.x + threadIdx.x;
    if (i >= E) return;
    int d = dst[i];
    int pos = rowstart[d] + atomicAdd(&cursor[d], 1);
    colsrc[pos] = src[i];
}

// ---------------------------------------------------------------------------
// merged prep: x -> fp16, 4 transposed fp16 weight blocks, tmpint zeroing
// block ranges: [0, NXB)                -> x16
//               [NXB, +128)             -> bt0
//               [.., +128)              -> bt1
//               [.., +32)               -> bts2
//               [.., +32)               -> btn2
//               [.., +NZB)              -> zero tmpint (int4)
// ---------------------------------------------------------------------------
__global__ void prep_all_kernel(const float* __restrict__ x, __half* __restrict__ x16, int n4,
                                const float* __restrict__ Ws0, const float* __restrict__ Wn0,
                                __half* __restrict__ bt0,
                                const float* __restrict__ Ws1, const float* __restrict__ Wn1,
                                __half* __restrict__ bt1,
                                const float* __restrict__ Ws2, __half* __restrict__ bts2,
                                const float* __restrict__ Wn2, __half* __restrict__ btn2,
                                int* __restrict__ tmpint, int nzero4,
                                int NXB) {
    int b = blockIdx.x;
    if (b < NXB) {
        int i = b * 256 + threadIdx.x;          // float4 slots
        if (i >= n4) return;
        float4 v = *(const float4*)(x + (size_t)i * 4);
        __half2 h0 = __floats2half2_rn(v.x, v.y);
        __half2 h1 = __floats2half2_rn(v.z, v.w);
        uint2 u;
        u.x = *(uint32_t*)&h0;
        u.y = *(uint32_t*)&h1;
        *(uint2*)(x16 + (size_t)i * 4) = u;
        return;
    }
    b -= NXB;
    if (b < 256) {  // bt0 / bt1 (dual, K=256)
        const float* Ws;
        const float* Wn;
        __half* Bt;
        if (b < 128) { Ws = Ws0; Wn = Wn0; Bt = bt0; }
        else         { Ws = Ws1; Wn = Wn1; Bt = bt1; b -= 128; }
        int i = b * 256 + threadIdx.x;
        int n = i >> 8, k = i & 255;
        float v = (k < 128) ? Ws[k * 128 + n] : Wn[(k - 128) * 128 + n];
        Bt[n * 256 + k] = __float2half_rn(v);
        return;
    }
    b -= 256;
    if (b < 64) {   // bts2 / btn2 (single, K=128, BN=64)
        const float* W;
        __half* Bt;
        if (b < 32) { W = Ws2; Bt = bts2; }
        else        { W = Wn2; Bt = btn2; b -= 32; }
        int i = b * 256 + threadIdx.x;          // < 64*128 = 8192
        int n = i >> 7, k = i & 127;
        Bt[n * 128 + k] = __float2half_rn(W[k * 64 + n]);
        return;
    }
    b -= 64;
    {   // zero tmpint as int4
        int i = b * 256 + threadIdx.x;
        if (i < nzero4) *(int4*)(tmpint + (size_t)i * 4) = make_int4(0, 0, 0, 0);
    }
}

// ---------------------------------------------------------------------------
// gather128: 16 lanes per node (uint4 = 8 halves / lane). fp32 accumulation.
// ---------------------------------------------------------------------------
__device__ __forceinline__ void acc_u4(float* a, uint4 u) {
    float2 p0 = __half22float2(*(__half2*)&u.x);
    float2 p1 = __half22float2(*(__half2*)&u.y);
    float2 p2 = __half22float2(*(__half2*)&u.z);
    float2 p3 = __half22float2(*(__half2*)&u.w);
    a[0] += p0.x; a[1] += p0.y; a[2] += p1.x; a[3] += p1.y;
    a[4] += p2.x; a[5] += p2.y; a[6] += p3.x; a[7] += p3.y;
}

__device__ __forceinline__ uint4 pack8(const float* a, float id) {
    __half2 o0 = __floats2half2_rn(a[0] * id, a[1] * id);
    __half2 o1 = __floats2half2_rn(a[2] * id, a[3] * id);
    __half2 o2 = __floats2half2_rn(a[4] * id, a[5] * id);
    __half2 o3 = __floats2half2_rn(a[6] * id, a[7] * id);
    uint4 o;
    o.x = *(uint32_t*)&o0; o.y = *(uint32_t*)&o1;
    o.z = *(uint32_t*)&o2; o.w = *(uint32_t*)&o3;
    return o;
}

template <int FW>   // feature width in halves (128 or 64)
__global__ void gather_kernel(const __half* __restrict__ h,
                              const int* __restrict__ rowstart,
                              const int* __restrict__ colsrc,
                              const float* __restrict__ invdeg,
                              __half* __restrict__ agg, int N) {
    constexpr int LPN = FW / 8;                 // lanes per node (16 or 8)
    int node = (blockIdx.x * blockDim.x + threadIdx.x) / LPN;
    int lane = threadIdx.x % LPN;
    if (node >= N) return;
    int beg = rowstart[node];
    int end = rowstart[node + 1];

    const __half* hb = h + lane * 8;
    float acc[8];
#pragma unroll
    for (int i = 0; i < 8; i++) acc[i] = 0.f;

    int j = beg;
    for (; j + 4 <= end; j += 4) {
        int s0 = __ldg(colsrc + j + 0);
        int s1 = __ldg(colsrc + j + 1);
        int s2 = __ldg(colsrc + j + 2);
        int s3 = __ldg(colsrc + j + 3);
        uint4 u0 = *(const uint4*)(hb + (size_t)s0 * FW);
        uint4 u1 = *(const uint4*)(hb + (size_t)s1 * FW);
        uint4 u2 = *(const uint4*)(hb + (size_t)s2 * FW);
        uint4 u3 = *(const uint4*)(hb + (size_t)s3 * FW);
        acc_u4(acc, u0); acc_u4(acc, u1); acc_u4(acc, u2); acc_u4(acc, u3);
    }
    for (; j < end; j++) {
        int s = __ldg(colsrc + j);
        uint4 u = *(const uint4*)(hb + (size_t)s * FW);
        acc_u4(acc, u);
    }
    *(uint4*)(agg + (size_t)node * FW + lane * 8) = pack8(acc, invdeg[node]);
}

// ---------------------------------------------------------------------------
// fp16 MMA helper: m16n8k16, fp32 accumulate
// ---------------------------------------------------------------------------
__device__ __forceinline__ void mma_f16(float& c0, float& c1, float& c2, float& c3,
                                        uint32_t a0, uint32_t a1, uint32_t a2, uint32_t a3,
                                        uint32_t b0, uint32_t b1) {
    asm volatile(
        "mma.sync.aligned.m16n8k16.row.col.f32.f16.f16.f32 "
        "{%0,%1,%2,%3}, {%4,%5,%6,%7}, {%8,%9}, {%0,%1,%2,%3};\n"
        : "+f"(c0), "+f"(c1), "+f"(c2), "+f"(c3)
        : "r"(a0), "r"(a1), "r"(a2), "r"(a3), "r"(b0), "r"(b1));
}

// ---------------------------------------------------------------------------
// fp16 GEMM. DUAL: out = A1[M,128]@W1 + A2[M,128]@W2 (K=256, Bt [n][256]).
// single: out = A1[M,128]@W (K=128, Bt [n][128]).
// Optional epilogue: + G (fp16 [M,BN]) + bias, relu; out fp16 or fp32.
// Block 128 x BN, 256 threads = 8 warps (4m x 2n), warp tile 32 x BN/2.
// ---------------------------------------------------------------------------
template <int BN, bool DUAL, bool RELU, bool OUTHALF, bool ADDG, bool BIAS>
__launch_bounds__(256, 2)
__global__ void gemm_f16_kernel(const __half* __restrict__ A1,
                                const __half* __restrict__ A2,
                                const __half* __restrict__ Bt,
                                const __half* __restrict__ G,
                                const float* __restrict__ bias,
                                void* __restrict__ outv, int M) {
    constexpr int KT = 32;
    constexpr int NS = DUAL ? 8 : 4;
    constexpr int LDB = DUAL ? 256 : 128;
    constexpr int ST = 40;             // smem row stride in halves (80 B)
    constexpr int NF = BN / 16;
    constexpr int NBU = BN * 8 / 256;

    __shared__ __align__(16) __half As[2][128 * ST];
    __shared__ __align__(16) __half Bs[2][BN * ST];

    const int tid  = threadIdx.x;
    const int wid  = tid >> 5;
    const int lane = tid & 31;
    const int g    = lane >> 2;
    const int t4   = lane & 3;
    const int warpM = wid & 3;
    const int warpN = wid >> 2;
    const int rowBase = blockIdx.x * 128;

    float acc[2][NF][4];
#pragma unroll
    for (int mf = 0; mf < 2; mf++)
#pragma unroll
        for (int nf = 0; nf < NF; nf++)
#pragma unroll
            for (int r = 0; r < 4; r++) acc[mf][nf][r] = 0.f;

    uint2 ra[4];
    uint2 rb[NBU];

    // ---- prologue: stage 0 ----
    {
#pragma unroll
        for (int i = 0; i < 4; i++) {
            int f = tid + i * 256;
            int r = f >> 3, q = f & 7;
            int row = rowBase + r;
            uint2 v = make_uint2(0u, 0u);
            if (row < M) v = *(const uint2*)(A1 + (size_t)row * 128 + q * 4);
            *(uint2*)&As[0][r * ST + q * 4] = v;
        }
#pragma unroll
        for (int i = 0; i < NBU; i++) {
            int f = tid + i * 256;
            int n = f >> 3, q = f & 7;
            uint2 v = *(const uint2*)(Bt + (size_t)n * LDB + q * 4);
            *(uint2*)&Bs[0][n * ST + q * 4] = v;
        }
    }
    __syncthreads();

    // ---- main loop ----
#pragma unroll 1
    for (int s = 0; s < NS; s++) {
        const int buf = s & 1;

        if (s + 1 < NS) {
            const __half* A = (DUAL && (s + 1 >= 4)) ? A2 : A1;
            const int k0 = (DUAL ? ((s + 1) & 3) : (s + 1)) * KT;
#pragma unroll
            for (int i = 0; i < 4; i++) {
                int f = tid + i * 256;
                int r = f >> 3, q = f & 7;
                int row = rowBase + r;
                ra[i] = make_uint2(0u, 0u);
                if (row < M) ra[i] = *(const uint2*)(A + (size_t)row * 128 + k0 + q * 4);
            }
            const int kb0 = (s + 1) * KT;
#pragma unroll
            for (int i = 0; i < NBU; i++) {
                int f = tid + i * 256;
                int n = f >> 3, q = f & 7;
                rb[i] = *(const uint2*)(Bt + (size_t)n * LDB + kb0 + q * 4);
            }
        }

#pragma unroll
        for (int k16 = 0; k16 < 2; k16++) {
            const int kb = k16 * 16;
            uint32_t a[2][4];
#pragma unroll
            for (int mf = 0; mf < 2; mf++) {
                int r0 = warpM * 32 + mf * 16 + g;
                const __half* p0 = &As[buf][r0 * ST + kb + 2 * t4];
                const __half* p1 = &As[buf][(r0 + 8) * ST + kb + 2 * t4];
                a[mf][0] = *(const uint32_t*)(p0);
                a[mf][1] = *(const uint32_t*)(p1);
                a[mf][2] = *(const uint32_t*)(p0 + 8);
                a[mf][3] = *(const uint32_t*)(p1 + 8);
            }
#pragma unroll
            for (int nf = 0; nf < NF; nf++) {
                int cb = warpN * (BN / 2) + nf * 8 + g;
                const __half* pb = &Bs[buf][cb * ST + kb + 2 * t4];
                uint32_t b0 = *(const uint32_t*)(pb);
                uint32_t b1 = *(const uint32_t*)(pb + 8);
#pragma unroll
                for (int mf = 0; mf < 2; mf++) {
                    mma_f16(acc[mf][nf][0], acc[mf][nf][1],
                            acc[mf][nf][2], acc[mf][nf][3],
                            a[mf][0], a[mf][1], a[mf][2], a[mf][3], b0, b1);
                }
            }
        }

        if (s + 1 < NS) {
            const int nbuf = buf ^ 1;
#pragma unroll
            for (int i = 0; i < 4; i++) {
                int f = tid + i * 256;
                int r = f >> 3, q = f & 7;
                *(uint2*)&As[nbuf][r * ST + q * 4] = ra[i];
            }
#pragma unroll
            for (int i = 0; i < NBU; i++) {
                int f = tid + i * 256;
                int n = f >> 3, q = f & 7;
                *(uint2*)&Bs[nbuf][n * ST + q * 4] = rb[i];
            }
            __syncthreads();
        }
    }

    // ---- epilogue ----
#pragma unroll
    for (int nf = 0; nf < NF; nf++) {
        int col = warpN * (BN / 2) + nf * 8 + t4 * 2;
        float2 bv = make_float2(0.f, 0.f);
        if (BIAS) bv = *(const float2*)(bias + col);
#pragma unroll
        for (int mf = 0; mf < 2; mf++) {
            int r0 = rowBase + warpM * 32 + mf * 16 + g;
            float2 v0 = make_float2(acc[mf][nf][0] + bv.x, acc[mf][nf][1] + bv.y);
            float2 v1 = make_float2(acc[mf][nf][2] + bv.x, acc[mf][nf][3] + bv.y);
            if (r0 < M) {
                if (ADDG) {
                    __half2 gg = *(const __half2*)(G + (size_t)r0 * BN + col);
                    float2 gf = __half22float2(gg);
                    v0.x += gf.x; v0.y += gf.y;
                }
                if (RELU) { v0.x = fmaxf(v0.x, 0.f); v0.y = fmaxf(v0.y, 0.f); }
                if (OUTHALF) {
                    __half2 hh = __floats2half2_rn(v0.x, v0.y);
                    *(__half2*)((__half*)outv + (size_t)r0 * BN + col) = hh;
                } else {
                    *(float2*)((float*)outv + (size_t)r0 * BN + col) = v0;
                }
            }
            if (r0 + 8 < M) {
                if (ADDG) {
                    __half2 gg = *(const __half2*)(G + (size_t)(r0 + 8) * BN + col);
                    float2 gf = __half22float2(gg);
                    v1.x += gf.x; v1.y += gf.y;
                }
                if (RELU) { v1.x = fmaxf(v1.x, 0.f); v1.y = fmaxf(v1.y, 0.f); }
                if (OUTHALF) {
                    __half2 hh = __floats2half2_rn(v1.x, v1.y);
                    *(__half2*)((__half*)outv + (size_t)(r0 + 8) * BN + col) = hh;
                } else {
                    *(float2*)((float*)outv + (size_t)(r0 + 8) * BN + col) = v1;
                }
            }
        }
    }
}

// ---------------------------------------------------------------------------
// launch
// ---------------------------------------------------------------------------
extern "C" void kernel_launch(void* const* d_in, const int* in_sizes, int n_in,
                              void* d_out, int out_size) {
    const float* x   = (const float*)d_in[0];
    const int*   src = (const int*)d_in[1];
    const int*   dst = (const int*)d_in[2];
    const float* Ws0 = (const float*)d_in[3];
    const float* Wn0 = (const float*)d_in[4];
    const float* b0  = (const float*)d_in[5];
    const float* Ws1 = (const float*)d_in[6];
    const float* Wn1 = (const float*)d_in[7];
    const float* b1  = (const float*)d_in[8];
    const float* Ws2 = (const float*)d_in[9];
    const float* Wn2 = (const float*)d_in[10];
    const float* b2  = (const float*)d_in[11];
    float* out = (float*)d_out;

    const int M = in_sizes[0] / 128;   // 100000
    const int E = in_sizes[1];         // 1600000

    __half *x16, *h1, *h2, *agg, *y2, *bt0, *bt1, *bts2, *btn2;
    float *invdeg;
    int *tmpint, *rowstart, *colsrc, *blocksum;
    cudaGetSymbolAddress((void**)&x16, g_x16);
    cudaGetSymbolAddress((void**)&h1,  g_h1);
    cudaGetSymbolAddress((void**)&h2,  g_h2);
    cudaGetSymbolAddress((void**)&agg, g_agg);
    cudaGetSymbolAddress((void**)&y2,  g_y2);
    cudaGetSymbolAddress((void**)&bt0, g_bt0);
    cudaGetSymbolAddress((void**)&bt1, g_bt1);
    cudaGetSymbolAddress((void**)&bts2, g_bts2);
    cudaGetSymbolAddress((void**)&btn2, g_btn2);
    cudaGetSymbolAddress((void**)&invdeg, g_invdeg);
    cudaGetSymbolAddress((void**)&tmpint, g_tmpint);
    cudaGetSymbolAddress((void**)&rowstart, g_rowstart);
    cudaGetSymbolAddress((void**)&colsrc, g_colsrc);
    cudaGetSymbolAddress((void**)&blocksum, g_blocksum);

    int* degi   = tmpint;
    int* cursor = tmpint + MAXN;

    const int gemmBlocks    = (M + 127) / 128;
    const int edgeBlocks    = (E + 255) / 256;
    const int gather128Blks = (M * 16 + 255) / 256;
    const int gather64Blks  = (M * 8 + 255) / 256;
    const int scanBlocks    = (M + 255) / 256;
    const int NXB           = (M * 32 + 255) / 256;      // x16 float4 blocks
    const int NZ4           = (2 * MAXN) / 4;            // tmpint int4 count
    const int NZB           = (NZ4 + 255) / 256;

    // ---- merged prep (x->fp16, weights, zero degi/cursor) ----
    prep_all_kernel<<<NXB + 320 + NZB, 256>>>(x, x16, M * 32,
                                              Ws0, Wn0, bt0,
                                              Ws1, Wn1, bt1,
                                              Ws2, bts2, Wn2, btn2,
                                              tmpint, NZ4, NXB);

    // ---- CSR build (dst-sorted) ----
    count_deg_kernel<<<edgeBlocks, 256>>>(dst, degi, E);
    block_reduce_kernel<<<scanBlocks, 256>>>(degi, blocksum, M);
    scan_write_kernel<<<scanBlocks, 256>>>(degi, blocksum, rowstart, invdeg, M);
    fill_kernel<<<edgeBlocks, 256>>>(src, dst, rowstart, cursor, colsrc, E);

    // ---- layer 0: h1 = relu(x@Ws0 + agg(x)@Wn0 + b0) ----
    gather_kernel<128><<<gather128Blks, 256>>>(x16, rowstart, colsrc, invdeg, agg, M);
    gemm_f16_kernel<128, true, true, true, false, true><<<gemmBlocks, 256>>>(
        x16, agg, bt0, nullptr, b0, h1, M);

    // ---- layer 1 ----
    gather_kernel<128><<<gather128Blks, 256>>>(h1, rowstart, colsrc, invdeg, agg, M);
    gemm_f16_kernel<128, true, true, true, false, true><<<gemmBlocks, 256>>>(
        h1, agg, bt1, nullptr, b1, h2, M);

    // ---- layer 2 (transform-first, 64-wide gather) ----
    gemm_f16_kernel<64, false, false, true, false, false><<<gemmBlocks, 256>>>(
        h2, nullptr, btn2, nullptr, nullptr, y2, M);       // y2 = h2@Wn2
    gather_kernel<64><<<gather64Blks, 256>>>(y2, rowstart, colsrc, invdeg, agg, M);
    gemm_f16_kernel<64, false, false, false, true, true><<<gemmBlocks, 256>>>(
        h2, nullptr, bts2, agg, b2, out, M);               // out = h2@Ws2 + G + b2
}

// round 13
// speedup vs baseline: 1.6681x; 1.0004x over previous
#include <cuda_runtime.h>
#include <cuda_fp16.h>
#include <cstdint>

// ---------------------------------------------------------------------------
// GraphSAGE, 3 layers, mean aggregation, fp16 data / fp32 accumulation.
// Layers 0/1: agg = mean h[src]; h' = relu([h|agg] @ [Ws;Wn] + b)  (dual-A)
// Layer 2 (transform-first, fused epilogue):
//   [y2|p2] = h2 @ [Wn2|Ws2]  (split GEMM: y2 fp16, p2 fp32 -> out)
//   out     = p2 + b2 + inv_deg * segment_sum(y2[src])   (gather64_final)
// CSR prefix sum: single-pass decoupled-lookback scan.
// ---------------------------------------------------------------------------

#define MAXN 100000
#define MAXE 1600000

__device__ __half g_x16[(size_t)MAXN * 128];
__device__ __half g_h1[(size_t)MAXN * 128];
__device__ __half g_h2[(size_t)MAXN * 128];
__device__ __half g_agg[(size_t)MAXN * 128];
__device__ __half g_y2[(size_t)MAXN * 64];
__device__ __half g_bt0[128 * 256];            // [n][k]: k<128 Ws, else Wn
__device__ __half g_bt1[128 * 256];
__device__ __half g_bt2c[128 * 128];           // [n][k]: n<64 Wn2, else Ws2
__device__ float g_invdeg[MAXN];
__device__ int   g_tmpint[2 * MAXN];           // degi | cursor
__device__ int   g_rowstart[MAXN + 1];
__device__ int   g_colsrc[MAXE];
__device__ int   g_scanstate[1024];            // [0:512) aggregate, [512:1024) flag

// ---------------------------------------------------------------------------
// CSR build
// ---------------------------------------------------------------------------
__global__ void count_deg_kernel(const int* __restrict__ dst, int* __restrict__ degi, int E) {
    int i = blockIdx.x * blockDim.x + threadIdx.x;
    if (i < E) atomicAdd(&degi[dst[i]], 1);
}

// single-pass scan with decoupled lookback (flags pre-zeroed by prep_all)
__global__ void scan_fused_kernel(const int* __restrict__ degi,
                                  int* __restrict__ scanstate,
                                  int* __restrict__ rowstart,
                                  float* __restrict__ invdeg, int N) {
    __shared__ int s[256];
    __shared__ int red[256];
    const int t = threadIdx.x;
    const int b = blockIdx.x;
    const int i = b * 256 + t;

    int v = (i < N) ? degi[i] : 0;
    s[t] = v;
    __syncthreads();
    for (int off = 1; off < 256; off <<= 1) {
        int u = (t >= off) ? s[t - off] : 0;
        __syncthreads();
        s[t] += u;
        __syncthreads();
    }

    // publish this block's aggregate
    if (t == 0) {
        scanstate[b] = s[255];
        __threadfence();
        *((volatile int*)&scanstate[512 + b]) = 1;
    }

    // lookback: sum aggregates of all previous blocks (parallel over threads)
    int partial = 0;
    for (int j = t; j < b; j += 256) {
        while (*((volatile int*)&scanstate[512 + j]) == 0) { }
        partial += *((volatile int*)&scanstate[j]);
    }
    red[t] = partial;
    __syncthreads();
#pragma unroll
    for (int off = 128; off > 0; off >>= 1) {
        if (t < off) red[t] += red[t + off];
        __syncthreads();
    }
    const int blockoff = red[0];

    if (i < N) {
        int excl = s[t] - v + blockoff;
        rowstart[i] = excl;
        invdeg[i] = 1.0f / fmaxf((float)v, 1.0f);
        if (i == N - 1) rowstart[N] = excl + v;
    }
}

__global__ void fill_kernel(const int* __restrict__ src,
                            const int* __restrict__ dst,
                            const int* __restrict__ rowstart,
                            int* __restrict__ cursor,
                            int* __restrict__ colsrc, int E) {
    int i = blockIdx.x * blockDim.x + threadIdx.x;
    if (i >= E) return;
    int d = dst[i];
    int pos = rowstart[d] + atomicAdd(&cursor[d], 1);
    colsrc[pos] = src[i];
}

// ---------------------------------------------------------------------------
// merged prep: x->fp16, 3 transposed weight blocks, zero tmpint + scanstate
// block ranges: [0, NXB)       -> x16
//               [NXB, +128)    -> bt0
//               [.., +128)     -> bt1
//               [.., +64)      -> bt2c
//               [.., +NZB)     -> zero tmpint (int4)
//               last block     -> zero scanstate
// ---------------------------------------------------------------------------
__global__ void prep_all_kernel(const float* __restrict__ x, __half* __restrict__ x16, int n4,
                                const float* __restrict__ Ws0, const float* __restrict__ Wn0,
                                __half* __restrict__ bt0,
                                const float* __restrict__ Ws1, const float* __restrict__ Wn1,
                                __half* __restrict__ bt1,
                                const float* __restrict__ Ws2, const float* __restrict__ Wn2,
                                __half* __restrict__ bt2c,
                                int* __restrict__ tmpint, int nzero4,
                                int* __restrict__ scanstate,
                                int NXB, int NZB) {
    int b = blockIdx.x;
    if (b < NXB) {
        int i = b * 256 + threadIdx.x;          // float4 slots
        if (i >= n4) return;
        float4 v = *(const float4*)(x + (size_t)i * 4);
        __half2 h0 = __floats2half2_rn(v.x, v.y);
        __half2 h1 = __floats2half2_rn(v.z, v.w);
        uint2 u;
        u.x = *(uint32_t*)&h0;
        u.y = *(uint32_t*)&h1;
        *(uint2*)(x16 + (size_t)i * 4) = u;
        return;
    }
    b -= NXB;
    if (b < 256) {  // bt0 / bt1 (dual, K=256)
        const float* Ws;
        const float* Wn;
        __half* Bt;
        if (b < 128) { Ws = Ws0; Wn = Wn0; Bt = bt0; }
        else         { Ws = Ws1; Wn = Wn1; Bt = bt1; b -= 128; }
        int i = b * 256 + threadIdx.x;
        int n = i >> 8, k = i & 255;
        float v = (k < 128) ? Ws[k * 128 + n] : Wn[(k - 128) * 128 + n];
        Bt[n * 256 + k] = __float2half_rn(v);
        return;
    }
    b -= 256;
    if (b < 64) {   // bt2c: [128 n][128 k], n<64 -> Wn2, n>=64 -> Ws2
        int i = b * 256 + threadIdx.x;          // < 16384
        int n = i >> 7, k = i & 127;
        float v = (n < 64) ? Wn2[k * 64 + n] : Ws2[k * 64 + (n - 64)];
        bt2c[n * 128 + k] = __float2half_rn(v);
        return;
    }
    b -= 64;
    if (b < NZB) {  // zero tmpint as int4
        int i = b * 256 + threadIdx.x;
        if (i < nzero4) *(int4*)(tmpint + (size_t)i * 4) = make_int4(0, 0, 0, 0);
        return;
    }
    // last block: zero scanstate (1024 ints = 256 int4)
    *(int4*)(scanstate + (size_t)threadIdx.x * 4) = make_int4(0, 0, 0, 0);
}

// ---------------------------------------------------------------------------
// gather helpers
// ---------------------------------------------------------------------------
__device__ __forceinline__ void acc_u4(float* a, uint4 u) {
    float2 p0 = __half22float2(*(__half2*)&u.x);
    float2 p1 = __half22float2(*(__half2*)&u.y);
    float2 p2 = __half22float2(*(__half2*)&u.z);
    float2 p3 = __half22float2(*(__half2*)&u.w);
    a[0] += p0.x; a[1] += p0.y; a[2] += p1.x; a[3] += p1.y;
    a[4] += p2.x; a[5] += p2.y; a[6] += p3.x; a[7] += p3.y;
}

__device__ __forceinline__ uint4 pack8(const float* a, float id) {
    __half2 o0 = __floats2half2_rn(a[0] * id, a[1] * id);
    __half2 o1 = __floats2half2_rn(a[2] * id, a[3] * id);
    __half2 o2 = __floats2half2_rn(a[4] * id, a[5] * id);
    __half2 o3 = __floats2half2_rn(a[6] * id, a[7] * id);
    uint4 o;
    o.x = *(uint32_t*)&o0; o.y = *(uint32_t*)&o1;
    o.z = *(uint32_t*)&o2; o.w = *(uint32_t*)&o3;
    return o;
}

// gather128: 16 lanes per node (uint4 = 8 halves / lane). fp32 accumulation.
__global__ void gather_kernel(const __half* __restrict__ h,
                              const int* __restrict__ rowstart,
                              const int* __restrict__ colsrc,
                              const float* __restrict__ invdeg,
                              __half* __restrict__ agg, int N) {
    int node = (blockIdx.x * blockDim.x + threadIdx.x) >> 4;
    int lane = threadIdx.x & 15;
    if (node >= N) return;
    int beg = rowstart[node];
    int end = rowstart[node + 1];

    const __half* hb = h + lane * 8;
    float acc[8];
#pragma unroll
    for (int i = 0; i < 8; i++) acc[i] = 0.f;

    int j = beg;
    for (; j + 4 <= end; j += 4) {
        int s0 = __ldg(colsrc + j + 0);
        int s1 = __ldg(colsrc + j + 1);
        int s2 = __ldg(colsrc + j + 2);
        int s3 = __ldg(colsrc + j + 3);
        uint4 u0 = *(const uint4*)(hb + (size_t)s0 * 128);
        uint4 u1 = *(const uint4*)(hb + (size_t)s1 * 128);
        uint4 u2 = *(const uint4*)(hb + (size_t)s2 * 128);
        uint4 u3 = *(const uint4*)(hb + (size_t)s3 * 128);
        acc_u4(acc, u0); acc_u4(acc, u1); acc_u4(acc, u2); acc_u4(acc, u3);
    }
    for (; j < end; j++) {
        int s = __ldg(colsrc + j);
        uint4 u = *(const uint4*)(hb + (size_t)s * 128);
        acc_u4(acc, u);
    }
    *(uint4*)(agg + (size_t)node * 128 + lane * 8) = pack8(acc, invdeg[node]);
}

// gather64_final: 8 lanes/node over y2 [M,64] fp16; epilogue adds p2 (fp32,
// already resident in out) + bias; writes fp32 out.
__global__ void gather64_final_kernel(const __half* __restrict__ y2,
                                      const int* __restrict__ rowstart,
                                      const int* __restrict__ colsrc,
                                      const float* __restrict__ invdeg,
                                      const float* __restrict__ b2,
                                      float* __restrict__ out, int N) {
    int node = (blockIdx.x * blockDim.x + threadIdx.x) >> 3;
    int lane = threadIdx.x & 7;
    if (node >= N) return;
    int beg = rowstart[node];
    int end = rowstart[node + 1];

    const __half* hb = y2 + lane * 8;
    float acc[8];
#pragma unroll
    for (int i = 0; i < 8; i++) acc[i] = 0.f;

    int j = beg;
    for (; j + 4 <= end; j += 4) {
        int s0 = __ldg(colsrc + j + 0);
        int s1 = __ldg(colsrc + j + 1);
        int s2 = __ldg(colsrc + j + 2);
        int s3 = __ldg(colsrc + j + 3);
        uint4 u0 = *(const uint4*)(hb + (size_t)s0 * 64);
        uint4 u1 = *(const uint4*)(hb + (size_t)s1 * 64);
        uint4 u2 = *(const uint4*)(hb + (size_t)s2 * 64);
        uint4 u3 = *(const uint4*)(hb + (size_t)s3 * 64);
        acc_u4(acc, u0); acc_u4(acc, u1); acc_u4(acc, u2); acc_u4(acc, u3);
    }
    for (; j < end; j++) {
        int s = __ldg(colsrc + j);
        uint4 u = *(const uint4*)(hb + (size_t)s * 64);
        acc_u4(acc, u);
    }

    float id = invdeg[node];
    size_t base = (size_t)node * 64 + lane * 8;
    float4 p0 = *(const float4*)(out + base);
    float4 p1 = *(const float4*)(out + base + 4);
    float4 bv0 = *(const float4*)(b2 + lane * 8);
    float4 bv1 = *(const float4*)(b2 + lane * 8 + 4);
    float4 o0, o1;
    o0.x = p0.x + bv0.x + acc[0] * id;
    o0.y = p0.y + bv0.y + acc[1] * id;
    o0.z = p0.z + bv0.z + acc[2] * id;
    o0.w = p0.w + bv0.w + acc[3] * id;
    o1.x = p1.x + bv1.x + acc[4] * id;
    o1.y = p1.y + bv1.y + acc[5] * id;
    o1.z = p1.z + bv1.z + acc[6] * id;
    o1.w = p1.w + bv1.w + acc[7] * id;
    *(float4*)(out + base)     = o0;
    *(float4*)(out + base + 4) = o1;
}

// ---------------------------------------------------------------------------
// fp16 MMA helper: m16n8k16, fp32 accumulate
// ---------------------------------------------------------------------------
__device__ __forceinline__ void mma_f16(float& c0, float& c1, float& c2, float& c3,
                                        uint32_t a0, uint32_t a1, uint32_t a2, uint32_t a3,
                                        uint32_t b0, uint32_t b1) {
    asm volatile(
        "mma.sync.aligned.m16n8k16.row.col.f32.f16.f16.f32 "
        "{%0,%1,%2,%3}, {%4,%5,%6,%7}, {%8,%9}, {%0,%1,%2,%3};\n"
        : "+f"(c0), "+f"(c1), "+f"(c2), "+f"(c3)
        : "r"(a0), "r"(a1), "r"(a2), "r"(a3), "r"(b0), "r"(b1));
}

// ---------------------------------------------------------------------------
// fp16 GEMM. DUAL: out = A1@W1 + A2@W2 (K=256). else K=128.
// SPLIT (BN=128): cols 0-63 -> y2 fp16 (outv), cols 64-127 -> p2 fp32 (out2).
// Block 128 x BN, 256 threads = 8 warps (4m x 2n), warp tile 32 x BN/2.
// ---------------------------------------------------------------------------
template <int BN, bool DUAL, bool RELU, bool BIAS, bool SPLIT>
__launch_bounds__(256, 2)
__global__ void gemm_f16_kernel(const __half* __restrict__ A1,
                                const __half* __restrict__ A2,
                                const __half* __restrict__ Bt,
                                const float* __restrict__ bias,
                                __half* __restrict__ outv,
                                float* __restrict__ out2, int M) {
    constexpr int KT = 32;
    constexpr int NS = DUAL ? 8 : 4;
    constexpr int LDB = DUAL ? 256 : 128;
    constexpr int ST = 40;
    constexpr int NF = BN / 16;
    constexpr int NBU = BN * 8 / 256;

    __shared__ __align__(16) __half As[2][128 * ST];
    __shared__ __align__(16) __half Bs[2][BN * ST];

    const int tid  = threadIdx.x;
    const int wid  = tid >> 5;
    const int lane = tid & 31;
    const int g    = lane >> 2;
    const int t4   = lane & 3;
    const int warpM = wid & 3;
    const int warpN = wid >> 2;
    const int rowBase = blockIdx.x * 128;

    float acc[2][NF][4];
#pragma unroll
    for (int mf = 0; mf < 2; mf++)
#pragma unroll
        for (int nf = 0; nf < NF; nf++)
#pragma unroll
            for (int r = 0; r < 4; r++) acc[mf][nf][r] = 0.f;

    uint2 ra[4];
    uint2 rb[NBU];

    // ---- prologue: stage 0 ----
    {
#pragma unroll
        for (int i = 0; i < 4; i++) {
            int f = tid + i * 256;
            int r = f >> 3, q = f & 7;
            int row = rowBase + r;
            uint2 v = make_uint2(0u, 0u);
            if (row < M) v = *(const uint2*)(A1 + (size_t)row * 128 + q * 4);
            *(uint2*)&As[0][r * ST + q * 4] = v;
        }
#pragma unroll
        for (int i = 0; i < NBU; i++) {
            int f = tid + i * 256;
            int n = f >> 3, q = f & 7;
            uint2 v = *(const uint2*)(Bt + (size_t)n * LDB + q * 4);
            *(uint2*)&Bs[0][n * ST + q * 4] = v;
        }
    }
    __syncthreads();

    // ---- main loop ----
#pragma unroll 1
    for (int s = 0; s < NS; s++) {
        const int buf = s & 1;

        if (s + 1 < NS) {
            const __half* A = (DUAL && (s + 1 >= 4)) ? A2 : A1;
            const int k0 = (DUAL ? ((s + 1) & 3) : (s + 1)) * KT;
#pragma unroll
            for (int i = 0; i < 4; i++) {
                int f = tid + i * 256;
                int r = f >> 3, q = f & 7;
                int row = rowBase + r;
                ra[i] = make_uint2(0u, 0u);
                if (row < M) ra[i] = *(const uint2*)(A + (size_t)row * 128 + k0 + q * 4);
            }
            const int kb0 = (s + 1) * KT;
#pragma unroll
            for (int i = 0; i < NBU; i++) {
                int f = tid + i * 256;
                int n = f >> 3, q = f & 7;
                rb[i] = *(const uint2*)(Bt + (size_t)n * LDB + kb0 + q * 4);
            }
        }

#pragma unroll
        for (int k16 = 0; k16 < 2; k16++) {
            const int kb = k16 * 16;
            uint32_t a[2][4];
#pragma unroll
            for (int mf = 0; mf < 2; mf++) {
                int r0 = warpM * 32 + mf * 16 + g;
                const __half* p0 = &As[buf][r0 * ST + kb + 2 * t4];
                const __half* p1 = &As[buf][(r0 + 8) * ST + kb + 2 * t4];
                a[mf][0] = *(const uint32_t*)(p0);
                a[mf][1] = *(const uint32_t*)(p1);
                a[mf][2] = *(const uint32_t*)(p0 + 8);
                a[mf][3] = *(const uint32_t*)(p1 + 8);
            }
#pragma unroll
            for (int nf = 0; nf < NF; nf++) {
                int cb = warpN * (BN / 2) + nf * 8 + g;
                const __half* pb = &Bs[buf][cb * ST + kb + 2 * t4];
                uint32_t b0 = *(const uint32_t*)(pb);
                uint32_t b1 = *(const uint32_t*)(pb + 8);
#pragma unroll
                for (int mf = 0; mf < 2; mf++) {
                    mma_f16(acc[mf][nf][0], acc[mf][nf][1],
                            acc[mf][nf][2], acc[mf][nf][3],
                            a[mf][0], a[mf][1], a[mf][2], a[mf][3], b0, b1);
                }
            }
        }

        if (s + 1 < NS) {
            const int nbuf = buf ^ 1;
#pragma unroll
            for (int i = 0; i < 4; i++) {
                int f = tid + i * 256;
                int r = f >> 3, q = f & 7;
                *(uint2*)&As[nbuf][r * ST + q * 4] = ra[i];
            }
#pragma unroll
            for (int i = 0; i < NBU; i++) {
                int f = tid + i * 256;
                int n = f >> 3, q = f & 7;
                *(uint2*)&Bs[nbuf][n * ST + q * 4] = rb[i];
            }
            __syncthreads();
        }
    }

    // ---- epilogue ----
#pragma unroll
    for (int nf = 0; nf < NF; nf++) {
        int col = warpN * (BN / 2) + nf * 8 + t4 * 2;
        float2 bv = make_float2(0.f, 0.f);
        if (BIAS) bv = *(const float2*)(bias + col);
#pragma unroll
        for (int mf = 0; mf < 2; mf++) {
            int r0 = rowBase + warpM * 32 + mf * 16 + g;
            float2 v0 = make_float2(acc[mf][nf][0] + bv.x, acc[mf][nf][1] + bv.y);
            float2 v1 = make_float2(acc[mf][nf][2] + bv.x, acc[mf][nf][3] + bv.y);
            if (RELU) {
                v0.x = fmaxf(v0.x, 0.f); v0.y = fmaxf(v0.y, 0.f);
                v1.x = fmaxf(v1.x, 0.f); v1.y = fmaxf(v1.y, 0.f);
            }
            if (SPLIT) {
                // cols [0,64): y2 fp16 ; cols [64,128): p2 fp32 -> out2
                if (warpN == 0) {
                    if (r0 < M) {
                        __half2 hh = __floats2half2_rn(v0.x, v0.y);
                        *(__half2*)(outv + (size_t)r0 * 64 + col) = hh;
                    }
                    if (r0 + 8 < M) {
                        __half2 hh = __floats2half2_rn(v1.x, v1.y);
                        *(__half2*)(outv + (size_t)(r0 + 8) * 64 + col) = hh;
                    }
                } else {
                    int c2 = col - 64;
                    if (r0 < M)     *(float2*)(out2 + (size_t)r0 * 64 + c2)       = v0;
                    if (r0 + 8 < M) *(float2*)(out2 + (size_t)(r0 + 8) * 64 + c2) = v1;
                }
            } else {
                if (r0 < M) {
                    __half2 hh = __floats2half2_rn(v0.x, v0.y);
                    *(__half2*)(outv + (size_t)r0 * BN + col) = hh;
                }
                if (r0 + 8 < M) {
                    __half2 hh = __floats2half2_rn(v1.x, v1.y);
                    *(__half2*)(outv + (size_t)(r0 + 8) * BN + col) = hh;
                }
            }
        }
    }
}

// ---------------------------------------------------------------------------
// launch
// ---------------------------------------------------------------------------
extern "C" void kernel_launch(void* const* d_in, const int* in_sizes, int n_in,
                              void* d_out, int out_size) {
    const float* x   = (const float*)d_in[0];
    const int*   src = (const int*)d_in[1];
    const int*   dst = (const int*)d_in[2];
    const float* Ws0 = (const float*)d_in[3];
    const float* Wn0 = (const float*)d_in[4];
    const float* b0  = (const float*)d_in[5];
    const float* Ws1 = (const float*)d_in[6];
    const float* Wn1 = (const float*)d_in[7];
    const float* b1  = (const float*)d_in[8];
    const float* Ws2 = (const float*)d_in[9];
    const float* Wn2 = (const float*)d_in[10];
    const float* b2  = (const float*)d_in[11];
    float* out = (float*)d_out;

    const int M = in_sizes[0] / 128;   // 100000
    const int E = in_sizes[1];         // 1600000

    __half *x16, *h1, *h2, *agg, *y2, *bt0, *bt1, *bt2c;
    float *invdeg;
    int *tmpint, *rowstart, *colsrc, *scanstate;
    cudaGetSymbolAddress((void**)&x16, g_x16);
    cudaGetSymbolAddress((void**)&h1,  g_h1);
    cudaGetSymbolAddress((void**)&h2,  g_h2);
    cudaGetSymbolAddress((void**)&agg, g_agg);
    cudaGetSymbolAddress((void**)&y2,  g_y2);
    cudaGetSymbolAddress((void**)&bt0, g_bt0);
    cudaGetSymbolAddress((void**)&bt1, g_bt1);
    cudaGetSymbolAddress((void**)&bt2c, g_bt2c);
    cudaGetSymbolAddress((void**)&invdeg, g_invdeg);
    cudaGetSymbolAddress((void**)&tmpint, g_tmpint);
    cudaGetSymbolAddress((void**)&rowstart, g_rowstart);
    cudaGetSymbolAddress((void**)&colsrc, g_colsrc);
    cudaGetSymbolAddress((void**)&scanstate, g_scanstate);

    int* degi   = tmpint;
    int* cursor = tmpint + MAXN;

    const int gemmBlocks    = (M + 127) / 128;
    const int edgeBlocks    = (E + 255) / 256;
    const int gather128Blks = (M * 16 + 255) / 256;
    const int gather64Blks  = (M * 8 + 255) / 256;
    const int scanBlocks    = (M + 255) / 256;
    const int NXB           = (M * 32 + 255) / 256;   // x16 float4 blocks
    const int NZ4           = (2 * MAXN) / 4;         // tmpint int4 count
    const int NZB           = (NZ4 + 255) / 256;

    // ---- merged prep ----
    prep_all_kernel<<<NXB + 320 + NZB + 1, 256>>>(x, x16, M * 32,
                                                  Ws0, Wn0, bt0,
                                                  Ws1, Wn1, bt1,
                                                  Ws2, Wn2, bt2c,
                                                  tmpint, NZ4, scanstate,
                                                  NXB, NZB);

    // ---- CSR build (dst-sorted) ----
    count_deg_kernel<<<edgeBlocks, 256>>>(dst, degi, E);
    scan_fused_kernel<<<scanBlocks, 256>>>(degi, scanstate, rowstart, invdeg, M);
    fill_kernel<<<edgeBlocks, 256>>>(src, dst, rowstart, cursor, colsrc, E);

    // ---- layer 0: h1 = relu(x@Ws0 + agg(x)@Wn0 + b0) ----
    gather_kernel<<<gather128Blks, 256>>>(x16, rowstart, colsrc, invdeg, agg, M);
    gemm_f16_kernel<128, true, true, true, false><<<gemmBlocks, 256>>>(
        x16, agg, bt0, b0, h1, nullptr, M);

    // ---- layer 1 ----
    gather_kernel<<<gather128Blks, 256>>>(h1, rowstart, colsrc, invdeg, agg, M);
    gemm_f16_kernel<128, true, true, true, false><<<gemmBlocks, 256>>>(
        h1, agg, bt1, b1, h2, nullptr, M);

    // ---- layer 2: [y2|p2] = h2 @ [Wn2|Ws2]; out = p2 + b2 + mean y2[src] ----
    gemm_f16_kernel<128, false, false, false, true><<<gemmBlocks, 256>>>(
        h2, nullptr, bt2c, nullptr, y2, out, M);
    gather64_final_kernel<<<gather64Blks, 256>>>(y2, rowstart, colsrc, invdeg,
                                                 b2, out, M);
}

// round 14
// speedup vs baseline: 1.7231x; 1.0330x over previous
#include <cuda_runtime.h>
#include <cuda_fp16.h>
#include <cstdint>

// ---------------------------------------------------------------------------
// GraphSAGE, 3 layers, mean aggregation, fp16 data / fp32 accumulation.
// Layers 0/1: agg = mean h[src]; h' = relu([h|agg] @ [Ws;Wn] + b)  (dual-A)
// Layer 2:    [y2|p2] = h2 @ [Wn2|Ws2]; out = p2 + b2 + mean y2[src]
// CSR: count merged into prep grid; single-pass lookback scan; cursor-free
// fill (atomicSub on degi). All dependent kernels use PDL to hide launch
// boundaries; GEMM prefetches weight tiles pre-sync.
// ---------------------------------------------------------------------------

#define MAXN 100000
#define MAXE 1600000

__device__ __half g_x16[(size_t)MAXN * 128];
__device__ __half g_h1[(size_t)MAXN * 128];
__device__ __half g_h2[(size_t)MAXN * 128];
__device__ __half g_agg[(size_t)MAXN * 128];
__device__ __half g_y2[(size_t)MAXN * 64];
__device__ __half g_bt0[128 * 256];            // [n][k]: k<128 Ws, else Wn
__device__ __half g_bt1[128 * 256];
__device__ __half g_bt2c[128 * 128];           // [n][k]: n<64 Wn2, else Ws2
__device__ float g_invdeg[MAXN];
__device__ int   g_degi[MAXN];
__device__ int   g_rowstart[MAXN + 1];
__device__ int   g_colsrc[MAXE];
__device__ int   g_scanstate[1024];            // [0:512) aggregate, [512:1024) flag

// ---------------------------------------------------------------------------
// merged prep: x->fp16, weights, scanstate zero, degree count (degi pre-zeroed)
// block ranges: [0, NXB)       -> x16
//               [NXB, +128)    -> bt0
//               [.., +128)     -> bt1
//               [.., +64)      -> bt2c
//               [.., +1)       -> zero scanstate
//               [.., +NEB)     -> count_deg over edges
// ---------------------------------------------------------------------------
__global__ void prep_all_kernel(const float* __restrict__ x, __half* __restrict__ x16, int n4,
                                const float* __restrict__ Ws0, const float* __restrict__ Wn0,
                                __half* __restrict__ bt0,
                                const float* __restrict__ Ws1, const float* __restrict__ Wn1,
                                __half* __restrict__ bt1,
                                const float* __restrict__ Ws2, const float* __restrict__ Wn2,
                                __half* __restrict__ bt2c,
                                int* __restrict__ scanstate,
                                const int* __restrict__ dst, int* __restrict__ degi, int E,
                                int NXB) {
    int b = blockIdx.x;
    if (b < NXB) {
        int i = b * 256 + threadIdx.x;          // float4 slots
        if (i >= n4) return;
        float4 v = *(const float4*)(x + (size_t)i * 4);
        __half2 h0 = __floats2half2_rn(v.x, v.y);
        __half2 h1 = __floats2half2_rn(v.z, v.w);
        uint2 u;
        u.x = *(uint32_t*)&h0;
        u.y = *(uint32_t*)&h1;
        *(uint2*)(x16 + (size_t)i * 4) = u;
        return;
    }
    b -= NXB;
    if (b < 256) {  // bt0 / bt1 (dual, K=256)
        const float* Ws;
        const float* Wn;
        __half* Bt;
        if (b < 128) { Ws = Ws0; Wn = Wn0; Bt = bt0; }
        else         { Ws = Ws1; Wn = Wn1; Bt = bt1; b -= 128; }
        int i = b * 256 + threadIdx.x;
        int n = i >> 8, k = i & 255;
        float v = (k < 128) ? Ws[k * 128 + n] : Wn[(k - 128) * 128 + n];
        Bt[n * 256 + k] = __float2half_rn(v);
        return;
    }
    b -= 256;
    if (b < 64) {   // bt2c: [128 n][128 k], n<64 -> Wn2, n>=64 -> Ws2
        int i = b * 256 + threadIdx.x;
        int n = i >> 7, k = i & 127;
        float v = (n < 64) ? Wn2[k * 64 + n] : Ws2[k * 64 + (n - 64)];
        bt2c[n * 128 + k] = __float2half_rn(v);
        return;
    }
    b -= 64;
    if (b == 0) {   // zero scanstate (1024 ints = 256 int4)
        *(int4*)(scanstate + (size_t)threadIdx.x * 4) = make_int4(0, 0, 0, 0);
        return;
    }
    b -= 1;
    {   // count_deg
        int i = b * 256 + threadIdx.x;
        if (i < E) atomicAdd(&degi[dst[i]], 1);
    }
}

// ---------------------------------------------------------------------------
// single-pass scan with decoupled lookback
// ---------------------------------------------------------------------------
__global__ void scan_fused_kernel(const int* __restrict__ degi,
                                  int* __restrict__ scanstate,
                                  int* __restrict__ rowstart,
                                  float* __restrict__ invdeg, int N) {
    cudaTriggerProgrammaticLaunchCompletion();
    cudaGridDependencySynchronize();

    __shared__ int s[256];
    __shared__ int red[256];
    const int t = threadIdx.x;
    const int b = blockIdx.x;
    const int i = b * 256 + t;

    int v = (i < N) ? degi[i] : 0;
    s[t] = v;
    __syncthreads();
    for (int off = 1; off < 256; off <<= 1) {
        int u = (t >= off) ? s[t - off] : 0;
        __syncthreads();
        s[t] += u;
        __syncthreads();
    }

    if (t == 0) {
        scanstate[b] = s[255];
        __threadfence();
        *((volatile int*)&scanstate[512 + b]) = 1;
    }

    int partial = 0;
    for (int j = t; j < b; j += 256) {
        while (*((volatile int*)&scanstate[512 + j]) == 0) { }
        partial += *((volatile int*)&scanstate[j]);
    }
    red[t] = partial;
    __syncthreads();
#pragma unroll
    for (int off = 128; off > 0; off >>= 1) {
        if (t < off) red[t] += red[t + off];
        __syncthreads();
    }
    const int blockoff = red[0];

    if (i < N) {
        int excl = s[t] - v + blockoff;
        rowstart[i] = excl;
        invdeg[i] = 1.0f / fmaxf((float)v, 1.0f);
        if (i == N - 1) rowstart[N] = excl + v;
    }
}

// cursor-free fill: degi (post-scan) doubles as down-counter
__global__ void fill_kernel(const int* __restrict__ src,
                            const int* __restrict__ dst,
                            const int* __restrict__ rowstart,
                            int* __restrict__ degi,
                            int* __restrict__ colsrc, int E) {
    cudaTriggerProgrammaticLaunchCompletion();
    int i = blockIdx.x * blockDim.x + threadIdx.x;
    int s = 0, d = 0;
    if (i < E) { s = src[i]; d = dst[i]; }     // inputs: safe pre-sync
    cudaGridDependencySynchronize();
    if (i >= E) return;
    int pos = rowstart[d] + atomicSub(&degi[d], 1) - 1;
    colsrc[pos] = s;
}

// ---------------------------------------------------------------------------
// gather helpers
// ---------------------------------------------------------------------------
__device__ __forceinline__ void acc_u4(float* a, uint4 u) {
    float2 p0 = __half22float2(*(__half2*)&u.x);
    float2 p1 = __half22float2(*(__half2*)&u.y);
    float2 p2 = __half22float2(*(__half2*)&u.z);
    float2 p3 = __half22float2(*(__half2*)&u.w);
    a[0] += p0.x; a[1] += p0.y; a[2] += p1.x; a[3] += p1.y;
    a[4] += p2.x; a[5] += p2.y; a[6] += p3.x; a[7] += p3.y;
}

__device__ __forceinline__ uint4 pack8(const float* a, float id) {
    __half2 o0 = __floats2half2_rn(a[0] * id, a[1] * id);
    __half2 o1 = __floats2half2_rn(a[2] * id, a[3] * id);
    __half2 o2 = __floats2half2_rn(a[4] * id, a[5] * id);
    __half2 o3 = __floats2half2_rn(a[6] * id, a[7] * id);
    uint4 o;
    o.x = *(uint32_t*)&o0; o.y = *(uint32_t*)&o1;
    o.z = *(uint32_t*)&o2; o.w = *(uint32_t*)&o3;
    return o;
}

// gather128: 16 lanes per node (uint4 = 8 halves / lane). fp32 accumulation.
__global__ void gather_kernel(const __half* __restrict__ h,
                              const int* __restrict__ rowstart,
                              const int* __restrict__ colsrc,
                              const float* __restrict__ invdeg,
                              __half* __restrict__ agg, int N) {
    cudaTriggerProgrammaticLaunchCompletion();
    cudaGridDependencySynchronize();

    int node = (blockIdx.x * blockDim.x + threadIdx.x) >> 4;
    int lane = threadIdx.x & 15;
    if (node >= N) return;
    int beg = rowstart[node];
    int end = rowstart[node + 1];

    const __half* hb = h + lane * 8;
    float acc[8];
#pragma unroll
    for (int i = 0; i < 8; i++) acc[i] = 0.f;

    int j = beg;
    for (; j + 4 <= end; j += 4) {
        int s0 = __ldg(colsrc + j + 0);
        int s1 = __ldg(colsrc + j + 1);
        int s2 = __ldg(colsrc + j + 2);
        int s3 = __ldg(colsrc + j + 3);
        uint4 u0 = *(const uint4*)(hb + (size_t)s0 * 128);
        uint4 u1 = *(const uint4*)(hb + (size_t)s1 * 128);
        uint4 u2 = *(const uint4*)(hb + (size_t)s2 * 128);
        uint4 u3 = *(const uint4*)(hb + (size_t)s3 * 128);
        acc_u4(acc, u0); acc_u4(acc, u1); acc_u4(acc, u2); acc_u4(acc, u3);
    }
    for (; j < end; j++) {
        int s = __ldg(colsrc + j);
        uint4 u = *(const uint4*)(hb + (size_t)s * 128);
        acc_u4(acc, u);
    }
    *(uint4*)(agg + (size_t)node * 128 + lane * 8) = pack8(acc, invdeg[node]);
}

// gather64_final: 8 lanes/node over y2; adds p2 (fp32, resident in out) + bias.
__global__ void gather64_final_kernel(const __half* __restrict__ y2,
                                      const int* __restrict__ rowstart,
                                      const int* __restrict__ colsrc,
                                      const float* __restrict__ invdeg,
                                      const float* __restrict__ b2,
                                      float* __restrict__ out, int N) {
    cudaTriggerProgrammaticLaunchCompletion();
    cudaGridDependencySynchronize();

    int node = (blockIdx.x * blockDim.x + threadIdx.x) >> 3;
    int lane = threadIdx.x & 7;
    if (node >= N) return;
    int beg = rowstart[node];
    int end = rowstart[node + 1];

    const __half* hb = y2 + lane * 8;
    float acc[8];
#pragma unroll
    for (int i = 0; i < 8; i++) acc[i] = 0.f;

    int j = beg;
    for (; j + 4 <= end; j += 4) {
        int s0 = __ldg(colsrc + j + 0);
        int s1 = __ldg(colsrc + j + 1);
        int s2 = __ldg(colsrc + j + 2);
        int s3 = __ldg(colsrc + j + 3);
        uint4 u0 = *(const uint4*)(hb + (size_t)s0 * 64);
        uint4 u1 = *(const uint4*)(hb + (size_t)s1 * 64);
        uint4 u2 = *(const uint4*)(hb + (size_t)s2 * 64);
        uint4 u3 = *(const uint4*)(hb + (size_t)s3 * 64);
        acc_u4(acc, u0); acc_u4(acc, u1); acc_u4(acc, u2); acc_u4(acc, u3);
    }
    for (; j < end; j++) {
        int s = __ldg(colsrc + j);
        uint4 u = *(const uint4*)(hb + (size_t)s * 64);
        acc_u4(acc, u);
    }

    float id = invdeg[node];
    size_t base = (size_t)node * 64 + lane * 8;
    float4 p0 = *(const float4*)(out + base);
    float4 p1 = *(const float4*)(out + base + 4);
    float4 bv0 = *(const float4*)(b2 + lane * 8);
    float4 bv1 = *(const float4*)(b2 + lane * 8 + 4);
    float4 o0, o1;
    o0.x = p0.x + bv0.x + acc[0] * id;
    o0.y = p0.y + bv0.y + acc[1] * id;
    o0.z = p0.z + bv0.z + acc[2] * id;
    o0.w = p0.w + bv0.w + acc[3] * id;
    o1.x = p1.x + bv1.x + acc[4] * id;
    o1.y = p1.y + bv1.y + acc[5] * id;
    o1.z = p1.z + bv1.z + acc[6] * id;
    o1.w = p1.w + bv1.w + acc[7] * id;
    *(float4*)(out + base)     = o0;
    *(float4*)(out + base + 4) = o1;
}

// ---------------------------------------------------------------------------
// fp16 MMA helper: m16n8k16, fp32 accumulate
// ---------------------------------------------------------------------------
__device__ __forceinline__ void mma_f16(float& c0, float& c1, float& c2, float& c3,
                                        uint32_t a0, uint32_t a1, uint32_t a2, uint32_t a3,
                                        uint32_t b0, uint32_t b1) {
    asm volatile(
        "mma.sync.aligned.m16n8k16.row.col.f32.f16.f16.f32 "
        "{%0,%1,%2,%3}, {%4,%5,%6,%7}, {%8,%9}, {%0,%1,%2,%3};\n"
        : "+f"(c0), "+f"(c1), "+f"(c2), "+f"(c3)
        : "r"(a0), "r"(a1), "r"(a2), "r"(a3), "r"(b0), "r"(b1));
}

// ---------------------------------------------------------------------------
// fp16 GEMM. DUAL: out = A1@W1 + A2@W2 (K=256). else K=128.
// SPLIT (BN=128): cols 0-63 -> y2 fp16 (outv), cols 64-127 -> p2 fp32 (out2).
// PDL: weight stage-0 loads issued pre-sync (weights are prep-era data).
// ---------------------------------------------------------------------------
template <int BN, bool DUAL, bool RELU, bool BIAS, bool SPLIT>
__launch_bounds__(256, 2)
__global__ void gemm_f16_kernel(const __half* __restrict__ A1,
                                const __half* __restrict__ A2,
                                const __half* __restrict__ Bt,
                                const float* __restrict__ bias,
                                __half* __restrict__ outv,
                                float* __restrict__ out2, int M) {
    constexpr int KT = 32;
    constexpr int NS = DUAL ? 8 : 4;
    constexpr int LDB = DUAL ? 256 : 128;
    constexpr int ST = 40;
    constexpr int NF = BN / 16;
    constexpr int NBU = BN * 8 / 256;

    __shared__ __align__(16) __half As[2][128 * ST];
    __shared__ __align__(16) __half Bs[2][BN * ST];

    const int tid  = threadIdx.x;
    const int wid  = tid >> 5;
    const int lane = tid & 31;
    const int g    = lane >> 2;
    const int t4   = lane & 3;
    const int warpM = wid & 3;
    const int warpN = wid >> 2;
    const int rowBase = blockIdx.x * 128;

    cudaTriggerProgrammaticLaunchCompletion();

    float acc[2][NF][4];
#pragma unroll
    for (int mf = 0; mf < 2; mf++)
#pragma unroll
        for (int nf = 0; nf < NF; nf++)
#pragma unroll
            for (int r = 0; r < 4; r++) acc[mf][nf][r] = 0.f;

    uint2 ra[4];
    uint2 rb[NBU];

    // ---- pre-sync: stage-0 weight loads (prep-era data, safe) ----
#pragma unroll
    for (int i = 0; i < NBU; i++) {
        int f = tid + i * 256;
        int n = f >> 3, q = f & 7;
        rb[i] = *(const uint2*)(Bt + (size_t)n * LDB + q * 4);
    }

    cudaGridDependencySynchronize();

    // ---- stage-0 A loads + smem stores ----
    {
#pragma unroll
        for (int i = 0; i < 4; i++) {
            int f = tid + i * 256;
            int r = f >> 3, q = f & 7;
            int row = rowBase + r;
            uint2 v = make_uint2(0u, 0u);
            if (row < M) v = *(const uint2*)(A1 + (size_t)row * 128 + q * 4);
            *(uint2*)&As[0][r * ST + q * 4] = v;
        }
#pragma unroll
        for (int i = 0; i < NBU; i++) {
            int f = tid + i * 256;
            int n = f >> 3, q = f & 7;
            *(uint2*)&Bs[0][n * ST + q * 4] = rb[i];
        }
    }
    __syncthreads();

    // ---- main loop ----
#pragma unroll 1
    for (int s = 0; s < NS; s++) {
        const int buf = s & 1;

        if (s + 1 < NS) {
            const __half* A = (DUAL && (s + 1 >= 4)) ? A2 : A1;
            const int k0 = (DUAL ? ((s + 1) & 3) : (s + 1)) * KT;
#pragma unroll
            for (int i = 0; i < 4; i++) {
                int f = tid + i * 256;
                int r = f >> 3, q = f & 7;
                int row = rowBase + r;
                ra[i] = make_uint2(0u, 0u);
                if (row < M) ra[i] = *(const uint2*)(A + (size_t)row * 128 + k0 + q * 4);
            }
            const int kb0 = (s + 1) * KT;
#pragma unroll
            for (int i = 0; i < NBU; i++) {
                int f = tid + i * 256;
                int n = f >> 3, q = f & 7;
                rb[i] = *(const uint2*)(Bt + (size_t)n * LDB + kb0 + q * 4);
            }
        }

#pragma unroll
        for (int k16 = 0; k16 < 2; k16++) {
            const int kb = k16 * 16;
            uint32_t a[2][4];
#pragma unroll
            for (int mf = 0; mf < 2; mf++) {
                int r0 = warpM * 32 + mf * 16 + g;
                const __half* p0 = &As[buf][r0 * ST + kb + 2 * t4];
                const __half* p1 = &As[buf][(r0 + 8) * ST + kb + 2 * t4];
                a[mf][0] = *(const uint32_t*)(p0);
                a[mf][1] = *(const uint32_t*)(p1);
                a[mf][2] = *(const uint32_t*)(p0 + 8);
                a[mf][3] = *(const uint32_t*)(p1 + 8);
            }
#pragma unroll
            for (int nf = 0; nf < NF; nf++) {
                int cb = warpN * (BN / 2) + nf * 8 + g;
                const __half* pb = &Bs[buf][cb * ST + kb + 2 * t4];
                uint32_t b0 = *(const uint32_t*)(pb);
                uint32_t b1 = *(const uint32_t*)(pb + 8);
#pragma unroll
                for (int mf = 0; mf < 2; mf++) {
                    mma_f16(acc[mf][nf][0], acc[mf][nf][1],
                            acc[mf][nf][2], acc[mf][nf][3],
                            a[mf][0], a[mf][1], a[mf][2], a[mf][3], b0, b1);
                }
            }
        }

        if (s + 1 < NS) {
            const int nbuf = buf ^ 1;
#pragma unroll
            for (int i = 0; i < 4; i++) {
                int f = tid + i * 256;
                int r = f >> 3, q = f & 7;
                *(uint2*)&As[nbuf][r * ST + q * 4] = ra[i];
            }
#pragma unroll
            for (int i = 0; i < NBU; i++) {
                int f = tid + i * 256;
                int n = f >> 3, q = f & 7;
                *(uint2*)&Bs[nbuf][n * ST + q * 4] = rb[i];
            }
            __syncthreads();
        }
    }

    // ---- epilogue ----
#pragma unroll
    for (int nf = 0; nf < NF; nf++) {
        int col = warpN * (BN / 2) + nf * 8 + t4 * 2;
        float2 bv = make_float2(0.f, 0.f);
        if (BIAS) bv = *(const float2*)(bias + col);
#pragma unroll
        for (int mf = 0; mf < 2; mf++) {
            int r0 = rowBase + warpM * 32 + mf * 16 + g;
            float2 v0 = make_float2(acc[mf][nf][0] + bv.x, acc[mf][nf][1] + bv.y);
            float2 v1 = make_float2(acc[mf][nf][2] + bv.x, acc[mf][nf][3] + bv.y);
            if (RELU) {
                v0.x = fmaxf(v0.x, 0.f); v0.y = fmaxf(v0.y, 0.f);
                v1.x = fmaxf(v1.x, 0.f); v1.y = fmaxf(v1.y, 0.f);
            }
            if (SPLIT) {
                if (warpN == 0) {
                    if (r0 < M) {
                        __half2 hh = __floats2half2_rn(v0.x, v0.y);
                        *(__half2*)(outv + (size_t)r0 * 64 + col) = hh;
                    }
                    if (r0 + 8 < M) {
                        __half2 hh = __floats2half2_rn(v1.x, v1.y);
                        *(__half2*)(outv + (size_t)(r0 + 8) * 64 + col) = hh;
                    }
                } else {
                    int c2 = col - 64;
                    if (r0 < M)     *(float2*)(out2 + (size_t)r0 * 64 + c2)       = v0;
                    if (r0 + 8 < M) *(float2*)(out2 + (size_t)(r0 + 8) * 64 + c2) = v1;
                }
            } else {
                if (r0 < M) {
                    __half2 hh = __floats2half2_rn(v0.x, v0.y);
                    *(__half2*)(outv + (size_t)r0 * BN + col) = hh;
                }
                if (r0 + 8 < M) {
                    __half2 hh = __floats2half2_rn(v1.x, v1.y);
                    *(__half2*)(outv + (size_t)(r0 + 8) * BN + col) = hh;
                }
            }
        }
    }
}

// ---------------------------------------------------------------------------
// PDL launch helper
// ---------------------------------------------------------------------------
template <typename F, typename... Args>
static inline void launch_pdl(F kernel, int grid, Args... args) {
    cudaLaunchAttribute attr[1];
    attr[0].id = cudaLaunchAttributeProgrammaticStreamSerialization;
    attr[0].val.programmaticStreamSerializationAllowed = 1;
    cudaLaunchConfig_t cfg = {};
    cfg.gridDim = dim3(grid);
    cfg.blockDim = dim3(256);
    cfg.dynamicSmemBytes = 0;
    cfg.stream = 0;
    cfg.attrs = attr;
    cfg.numAttrs = 1;
    cudaLaunchKernelEx(&cfg, kernel, args...);
}

// ---------------------------------------------------------------------------
// launch
// ---------------------------------------------------------------------------
extern "C" void kernel_launch(void* const* d_in, const int* in_sizes, int n_in,
                              void* d_out, int out_size) {
    const float* x   = (const float*)d_in[0];
    const int*   src = (const int*)d_in[1];
    const int*   dst = (const int*)d_in[2];
    const float* Ws0 = (const float*)d_in[3];
    const float* Wn0 = (const float*)d_in[4];
    const float* b0  = (const float*)d_in[5];
    const float* Ws1 = (const float*)d_in[6];
    const float* Wn1 = (const float*)d_in[7];
    const float* b1  = (const float*)d_in[8];
    const float* Ws2 = (const float*)d_in[9];
    const float* Wn2 = (const float*)d_in[10];
    const float* b2  = (const float*)d_in[11];
    float* out = (float*)d_out;

    const int M = in_sizes[0] / 128;   // 100000
    const int E = in_sizes[1];         // 1600000

    __half *x16, *h1, *h2, *agg, *y2, *bt0, *bt1, *bt2c;
    float *invdeg;
    int *degi, *rowstart, *colsrc, *scanstate;
    cudaGetSymbolAddress((void**)&x16, g_x16);
    cudaGetSymbolAddress((void**)&h1,  g_h1);
    cudaGetSymbolAddress((void**)&h2,  g_h2);
    cudaGetSymbolAddress((void**)&agg, g_agg);
    cudaGetSymbolAddress((void**)&y2,  g_y2);
    cudaGetSymbolAddress((void**)&bt0, g_bt0);
    cudaGetSymbolAddress((void**)&bt1, g_bt1);
    cudaGetSymbolAddress((void**)&bt2c, g_bt2c);
    cudaGetSymbolAddress((void**)&invdeg, g_invdeg);
    cudaGetSymbolAddress((void**)&degi, g_degi);
    cudaGetSymbolAddress((void**)&rowstart, g_rowstart);
    cudaGetSymbolAddress((void**)&colsrc, g_colsrc);
    cudaGetSymbolAddress((void**)&scanstate, g_scanstate);

    const int gemmBlocks    = (M + 127) / 128;
    const int edgeBlocks    = (E + 255) / 256;
    const int gather128Blks = (M * 16 + 255) / 256;
    const int gather64Blks  = (M * 8 + 255) / 256;
    const int scanBlocks    = (M + 255) / 256;
    const int NXB           = (M * 32 + 255) / 256;   // x16 float4 blocks

    // ---- zero degi, then merged prep (includes count_deg) ----
    cudaMemsetAsync(degi, 0, (size_t)MAXN * sizeof(int));
    prep_all_kernel<<<NXB + 321 + edgeBlocks, 256>>>(
        x, x16, M * 32,
        Ws0, Wn0, bt0,
        Ws1, Wn1, bt1,
        Ws2, Wn2, bt2c,
        scanstate, dst, degi, E, NXB);

    // ---- CSR: scan + cursor-free fill ----
    launch_pdl(scan_fused_kernel, scanBlocks, (const int*)degi, scanstate,
               rowstart, invdeg, M);
    launch_pdl(fill_kernel, edgeBlocks, src, dst, (const int*)rowstart,
               degi, colsrc, E);

    // ---- layer 0: h1 = relu(x@Ws0 + agg(x)@Wn0 + b0) ----
    launch_pdl(gather_kernel, gather128Blks, (const __half*)x16,
               (const int*)rowstart, (const int*)colsrc,
               (const float*)invdeg, agg, M);
    launch_pdl(gemm_f16_kernel<128, true, true, true, false>, gemmBlocks,
               (const __half*)x16, (const __half*)agg, (const __half*)bt0,
               b0, h1, (float*)nullptr, M);

    // ---- layer 1 ----
    launch_pdl(gather_kernel, gather128Blks, (const __half*)h1,
               (const int*)rowstart, (const int*)colsrc,
               (const float*)invdeg, agg, M);
    launch_pdl(gemm_f16_kernel<128, true, true, true, false>, gemmBlocks,
               (const __half*)h1, (const __half*)agg, (const __half*)bt1,
               b1, h2, (float*)nullptr, M);

    // ---- layer 2: [y2|p2] = h2 @ [Wn2|Ws2]; out = p2 + b2 + mean y2[src] ----
    launch_pdl(gemm_f16_kernel<128, false, false, false, true>, gemmBlocks,
               (const __half*)h2, (const __half*)nullptr, (const __half*)bt2c,
               (const float*)nullptr, y2, out, M);
    launch_pdl(gather64_final_kernel, gather64Blks, (const __half*)y2,
               (const int*)rowstart, (const int*)colsrc,
               (const float*)invdeg, b2, out, M);
}